// round 13
// baseline (speedup 1.0000x reference)
#include <cuda_runtime.h>

#define NTOT 262152
#define CDIM 256
#define DFFN 1024
#define NSETS 7282
#define SETSZ 36
#define MTOT (2*2*NSETS*SETSZ)   // 1048608
#define NC   ((size_t)NTOT * CDIM)

// ------------------------- scratch (device globals; no allocation) -------------------------
// Single pool, 7*NC floats = 1.879 GB (keeps .bss inside aarch64 ±4GB reloc window).
// Layout:
//   [0,2NC)   qko   (Q|K after in-proj, set order)      } ffh (N x DFFN = 4NC)
//   [2NC,3NC) vproj (V after in-proj, voxel order)      }  aliases [0,4NC)
//   [3NC,4NC) att   (attention out, set order)          }  after attn+outproj
//   [4NC,5NC) qk -> proj -> ffo (time-multiplexed)
//   [5NC,6NC) bufA  (layer-0 output / x1 alias)
//   [6NC,7NC) bufB  (layer-1 output / x1 alias)
__device__ float g_pool[7 * NC];
__device__ unsigned char g_maskc[MTOT];
__device__ int g_mask_flag;

__device__ __forceinline__ float warp_sum(float v) {
#pragma unroll
    for (int o = 16; o; o >>= 1) v += __shfl_xor_sync(0xffffffffu, v, o);
    return v;
}

// ------------------------- mask dtype detection + canonicalization -------------------------
// uint8 bool : bytes nonzero at arbitrary positions  -> lo!=0, hi!=0
// int32 0/1  : only bytes j%4==0 nonzero             -> lo!=0, hi==0
// float32    : 1.0f = 00 00 80 3F, low byte zero     -> lo==0, hi!=0
__global__ void k_mask_detect(const unsigned char* __restrict__ raw) {
    __shared__ unsigned int slo[256], shi[256];
    unsigned int lo = 0, hi = 0;
    for (int i = threadIdx.x; i < 65536; i += 256) {
        unsigned int b = raw[i];
        if ((i & 3) == 0) lo |= b; else hi |= b;
    }
    slo[threadIdx.x] = lo; shi[threadIdx.x] = hi;
    __syncthreads();
    if (threadIdx.x == 0) {
        for (int i = 1; i < 256; i++) { lo |= slo[i]; hi |= shi[i]; }
        int flag;
        if (hi == 0)       flag = 1;   // int32
        else if (lo != 0)  flag = 0;   // uint8
        else               flag = 2;   // float32
        g_mask_flag = flag;
    }
}

__global__ void k_mask_convert(const unsigned char* __restrict__ raw) {
    int i = blockIdx.x * 256 + threadIdx.x;
    if (i >= MTOT) return;
    int f = g_mask_flag;
    unsigned char v;
    if (f == 0)      v = (raw[i] != 0);
    else if (f == 1) v = (((const int*)raw)[i] != 0);
    else             v = (((const float*)raw)[i] != 0.0f);
    g_maskc[i] = v;
}

// ------------------------- gather: qk = x[ind] + pos[ind] (set order) -------------------------
__global__ void __launch_bounds__(256) k_gather_qk(
    const float* __restrict__ x, const float* __restrict__ pos,
    const int* __restrict__ inds, float* __restrict__ qk)
{
    int idx = blockIdx.x * 256 + threadIdx.x;   // NTOT*64 threads exactly
    int r = idx >> 6;
    int c = idx & 63;
    int v = inds[r];
    float4 xv = ((const float4*)x)[(size_t)v * 64 + c];
    float4 pv = ((const float4*)pos)[(size_t)v * 64 + c];
    ((float4*)qk)[(size_t)r * 64 + c] =
        make_float4(xv.x + pv.x, xv.y + pv.y, xv.z + pv.z, xv.w + pv.w);
}

// ------------------------- fp32 SGEMM: C = A(MxK) @ W(NnxK)^T + bias, optional GELU -------------------------
#define BM 128
#define BN 128
#define BKK 16

__global__ void __launch_bounds__(256) k_sgemm(
    const float* __restrict__ A, const float* __restrict__ W,
    const float* __restrict__ bias, float* __restrict__ C,
    int M, int Nn, int K, int act)
{
    __shared__ __align__(16) float As[BKK][BM];
    __shared__ __align__(16) float Bs[BKK][BN];
    int tid  = threadIdx.x;
    int row0 = blockIdx.y * BM;
    int col0 = blockIdx.x * BN;
    int lr = tid >> 2;            // 0..63
    int lc = (tid & 3) << 2;      // 0,4,8,12
    int ty = tid >> 4;            // 0..15
    int tx = tid & 15;            // 0..15

    float acc[8][8];
#pragma unroll
    for (int i = 0; i < 8; i++)
#pragma unroll
        for (int j = 0; j < 8; j++) acc[i][j] = 0.f;

    const float* Wp = W + (size_t)col0 * K;

    for (int k0 = 0; k0 < K; k0 += BKK) {
#pragma unroll
        for (int rr = 0; rr < 2; rr++) {
            int r  = lr + rr * 64;
            int gr = row0 + r;
            float4 v = (gr < M) ? *(const float4*)(A + (size_t)gr * K + k0 + lc)
                                : make_float4(0.f, 0.f, 0.f, 0.f);
            As[lc + 0][r] = v.x; As[lc + 1][r] = v.y; As[lc + 2][r] = v.z; As[lc + 3][r] = v.w;
            float4 w = *(const float4*)(Wp + (size_t)r * K + k0 + lc);  // Nn multiple of 128
            Bs[lc + 0][r] = w.x; Bs[lc + 1][r] = w.y; Bs[lc + 2][r] = w.z; Bs[lc + 3][r] = w.w;
        }
        __syncthreads();
#pragma unroll
        for (int k = 0; k < BKK; k++) {
            float ra[8], rb[8];
            *(float4*)&ra[0] = *(const float4*)&As[k][ty * 8];
            *(float4*)&ra[4] = *(const float4*)&As[k][ty * 8 + 4];
            *(float4*)&rb[0] = *(const float4*)&Bs[k][tx * 8];
            *(float4*)&rb[4] = *(const float4*)&Bs[k][tx * 8 + 4];
#pragma unroll
            for (int i = 0; i < 8; i++)
#pragma unroll
                for (int j = 0; j < 8; j++) acc[i][j] += ra[i] * rb[j];
        }
        __syncthreads();
    }

    float4 b0 = *(const float4*)(bias + col0 + tx * 8);
    float4 b1 = *(const float4*)(bias + col0 + tx * 8 + 4);
    float bb[8] = {b0.x, b0.y, b0.z, b0.w, b1.x, b1.y, b1.z, b1.w};
#pragma unroll
    for (int i = 0; i < 8; i++) {
        int r = row0 + ty * 8 + i;
        if (r >= M) continue;
        float o[8];
#pragma unroll
        for (int j = 0; j < 8; j++) {
            float x = acc[i][j] + bb[j];
            if (act) x = 0.5f * x * (1.0f + erff(x * 0.70710678118654752f));  // exact GELU
            o[j] = x;
        }
        float* cp = C + (size_t)r * Nn + col0 + tx * 8;
        *(float4*)cp       = make_float4(o[0], o[1], o[2], o[3]);
        *(float4*)(cp + 4) = make_float4(o[4], o[5], o[6], o[7]);
    }
}

// ------------------------- per-set masked MHA -------------------------
// block = one set; 256 threads; pair p -> (h = p/36, l = p%36). K,V staged in SMEM.
// Q/K from qko (set order); V gathered from vproj (voxel order) via inds.
__global__ void __launch_bounds__(256) k_attn(
    const float* __restrict__ qko,    // N x 512 : [0:256)=Q, [256:512)=K (set order)
    const float* __restrict__ vproj,  // N x 256 (voxel order)
    const int* __restrict__ inds,
    const unsigned char* __restrict__ mask,
    float* __restrict__ out)          // N x 256 (set order)
{
    extern __shared__ float sm[];
    float* Ks = sm;                  // 36*256
    float* Vs = sm + SETSZ * CDIM;   // 36*256
    __shared__ unsigned char ms[SETSZ];
    __shared__ int vind[SETSZ];

    int s   = blockIdx.x;
    int tid = threadIdx.x;
    size_t base = (size_t)s * SETSZ;

    if (tid < SETSZ) { ms[tid] = mask[base + tid]; vind[tid] = inds[base + tid]; }
    __syncthreads();

    for (int i = tid; i < SETSZ * 64; i += 256) {
        int m = i >> 6, c = i & 63;
        ((float4*)Ks)[(size_t)m * 64 + c] = *((const float4*)(qko + (base + m) * 512 + 256) + c);
        ((float4*)Vs)[(size_t)m * 64 + c] = ((const float4*)vproj)[(size_t)vind[m] * 64 + c];
    }
    __syncthreads();

    for (int pair = tid; pair < SETSZ * 8; pair += 256) {
        int h = pair / SETSZ;   // lanes in a warp share h -> SMEM broadcast
        int l = pair % SETSZ;

        const float* qp = qko + (base + l) * 512 + h * 32;
        float q[32];
#pragma unroll
        for (int d = 0; d < 32; d += 4) {
            float4 t = *(const float4*)(qp + d);
            q[d] = t.x; q[d + 1] = t.y; q[d + 2] = t.z; q[d + 3] = t.w;
        }

        float sc[SETSZ];
        float mx = -1e30f;
#pragma unroll
        for (int m = 0; m < SETSZ; m++) {
            const float* kp = Ks + m * CDIM + h * 32;
            float a = 0.f;
#pragma unroll
            for (int d = 0; d < 32; d++) a += q[d] * kp[d];
            a *= 0.17677669529663687f;          // 1/sqrt(32)
            if (ms[m]) a = -1e30f;
            sc[m] = a;
            mx = fmaxf(mx, a);
        }
        float den = 0.f;
#pragma unroll
        for (int m = 0; m < SETSZ; m++) {
            float e = ms[m] ? 0.f : __expf(sc[m] - mx);
            sc[m] = e;
            den += e;
        }
        float inv = 1.0f / den;

        float o[32];
#pragma unroll
        for (int d = 0; d < 32; d++) o[d] = 0.f;
#pragma unroll
        for (int m = 0; m < SETSZ; m++) {
            float a = sc[m] * inv;
            const float* vp = Vs + m * CDIM + h * 32;
#pragma unroll
            for (int d = 0; d < 32; d++) o[d] += a * vp[d];
        }
        float* op = out + (base + l) * 256 + h * 32;
#pragma unroll
        for (int d = 0; d < 32; d += 4)
            *(float4*)(op + d) = make_float4(o[d], o[d + 1], o[d + 2], o[d + 3]);
    }
}

// ------------------------- scatter + residual + LN1 (warp per set-row) -------------------------
__global__ void __launch_bounds__(256) k_scatter_ln(
    const float* __restrict__ xin, const float* __restrict__ proj,
    const int* __restrict__ inds, const float* __restrict__ gam,
    const float* __restrict__ bet, float* __restrict__ out)
{
    int r = (blockIdx.x * 256 + threadIdx.x) >> 5;   // set-row, exact (NTOT/8 blocks)
    int lane = threadIdx.x & 31;
    int v = inds[r];
    const float4* x4 = (const float4*)(xin + (size_t)v * CDIM);
    const float4* p4 = (const float4*)(proj + (size_t)r * CDIM);
    float4 a0 = x4[lane],      b0 = p4[lane];
    float4 a1 = x4[lane + 32], b1 = p4[lane + 32];
    float4 y0 = make_float4(a0.x + b0.x, a0.y + b0.y, a0.z + b0.z, a0.w + b0.w);
    float4 y1 = make_float4(a1.x + b1.x, a1.y + b1.y, a1.z + b1.z, a1.w + b1.w);
    float s  = y0.x + y0.y + y0.z + y0.w + y1.x + y1.y + y1.z + y1.w;
    float s2 = y0.x*y0.x + y0.y*y0.y + y0.z*y0.z + y0.w*y0.w
             + y1.x*y1.x + y1.y*y1.y + y1.z*y1.z + y1.w*y1.w;
    s = warp_sum(s); s2 = warp_sum(s2);
    float mean = s * (1.0f / CDIM);
    float inv  = rsqrtf(s2 * (1.0f / CDIM) - mean * mean + 1e-5f);
    float4 g0 = ((const float4*)gam)[lane],      g1 = ((const float4*)gam)[lane + 32];
    float4 c0 = ((const float4*)bet)[lane],      c1 = ((const float4*)bet)[lane + 32];
    float4 o0 = make_float4((y0.x - mean) * inv * g0.x + c0.x, (y0.y - mean) * inv * g0.y + c0.y,
                            (y0.z - mean) * inv * g0.z + c0.z, (y0.w - mean) * inv * g0.w + c0.w);
    float4 o1 = make_float4((y1.x - mean) * inv * g1.x + c1.x, (y1.y - mean) * inv * g1.y + c1.y,
                            (y1.z - mean) * inv * g1.z + c1.z, (y1.w - mean) * inv * g1.w + c1.w);
    ((float4*)(out + (size_t)v * CDIM))[lane]      = o0;
    ((float4*)(out + (size_t)v * CDIM))[lane + 32] = o1;
}

// ------------------------- LN2 then LN3 fused (warp per voxel row) -------------------------
// NOTE: x1 and out may be the SAME buffer (row-wise read-then-write) -> no __restrict__ on them.
__global__ void __launch_bounds__(256) k_ln2_ln3(
    const float* x1, const float* __restrict__ ff,
    const float* __restrict__ idn,
    const float* __restrict__ g2, const float* __restrict__ b2,
    const float* __restrict__ g3, const float* __restrict__ b3,
    float* out)
{
    int r = (blockIdx.x * 256 + threadIdx.x) >> 5;
    int lane = threadIdx.x & 31;
    const float4* a4 = (const float4*)(x1 + (size_t)r * CDIM);
    const float4* f4 = (const float4*)(ff + (size_t)r * CDIM);
    float4 a0 = a4[lane],      c0 = f4[lane];
    float4 a1 = a4[lane + 32], c1 = f4[lane + 32];
    float4 y0 = make_float4(a0.x + c0.x, a0.y + c0.y, a0.z + c0.z, a0.w + c0.w);
    float4 y1 = make_float4(a1.x + c1.x, a1.y + c1.y, a1.z + c1.z, a1.w + c1.w);
    float s  = y0.x + y0.y + y0.z + y0.w + y1.x + y1.y + y1.z + y1.w;
    float s2 = y0.x*y0.x + y0.y*y0.y + y0.z*y0.z + y0.w*y0.w
             + y1.x*y1.x + y1.y*y1.y + y1.z*y1.z + y1.w*y1.w;
    s = warp_sum(s); s2 = warp_sum(s2);
    float mean = s * (1.0f / CDIM);
    float inv  = rsqrtf(s2 * (1.0f / CDIM) - mean * mean + 1e-5f);
    float4 g20 = ((const float4*)g2)[lane],      g21 = ((const float4*)g2)[lane + 32];
    float4 b20 = ((const float4*)b2)[lane],      b21 = ((const float4*)b2)[lane + 32];
    const float4* i4 = (const float4*)(idn + (size_t)r * CDIM);
    float4 i0 = i4[lane], i1 = i4[lane + 32];
    float4 z0 = make_float4((y0.x - mean) * inv * g20.x + b20.x + i0.x,
                            (y0.y - mean) * inv * g20.y + b20.y + i0.y,
                            (y0.z - mean) * inv * g20.z + b20.z + i0.z,
                            (y0.w - mean) * inv * g20.w + b20.w + i0.w);
    float4 z1 = make_float4((y1.x - mean) * inv * g21.x + b21.x + i1.x,
                            (y1.y - mean) * inv * g21.y + b21.y + i1.y,
                            (y1.z - mean) * inv * g21.z + b21.z + i1.z,
                            (y1.w - mean) * inv * g21.w + b21.w + i1.w);
    float t  = z0.x + z0.y + z0.z + z0.w + z1.x + z1.y + z1.z + z1.w;
    float t2 = z0.x*z0.x + z0.y*z0.y + z0.z*z0.z + z0.w*z0.w
             + z1.x*z1.x + z1.y*z1.y + z1.z*z1.z + z1.w*z1.w;
    t = warp_sum(t); t2 = warp_sum(t2);
    float mean2 = t * (1.0f / CDIM);
    float inv2  = rsqrtf(t2 * (1.0f / CDIM) - mean2 * mean2 + 1e-5f);
    float4 g30 = ((const float4*)g3)[lane],      g31 = ((const float4*)g3)[lane + 32];
    float4 b30 = ((const float4*)b3)[lane],      b31 = ((const float4*)b3)[lane + 32];
    float4 o0 = make_float4((z0.x - mean2) * inv2 * g30.x + b30.x, (z0.y - mean2) * inv2 * g30.y + b30.y,
                            (z0.z - mean2) * inv2 * g30.z + b30.z, (z0.w - mean2) * inv2 * g30.w + b30.w);
    float4 o1 = make_float4((z1.x - mean2) * inv2 * g31.x + b31.x, (z1.y - mean2) * inv2 * g31.y + b31.y,
                            (z1.z - mean2) * inv2 * g31.z + b31.z, (z1.w - mean2) * inv2 * g31.w + b31.w);
    ((float4*)(out + (size_t)r * CDIM))[lane]      = o0;
    ((float4*)(out + (size_t)r * CDIM))[lane + 32] = o1;
}

// ------------------------- block-end: LN(a + b) -------------------------
// b (blockin) and out may be the SAME buffer (row-wise read-then-write) -> no __restrict__.
__global__ void __launch_bounds__(256) k_add_ln(
    const float* __restrict__ a, const float* b,
    const float* __restrict__ g, const float* __restrict__ be,
    float* out)
{
    int r = (blockIdx.x * 256 + threadIdx.x) >> 5;
    int lane = threadIdx.x & 31;
    const float4* a4 = (const float4*)(a + (size_t)r * CDIM);
    const float4* b4 = (const float4*)(b + (size_t)r * CDIM);
    float4 x0 = a4[lane],      x1 = a4[lane + 32];
    float4 c0 = b4[lane],      c1 = b4[lane + 32];
    float4 y0 = make_float4(x0.x + c0.x, x0.y + c0.y, x0.z + c0.z, x0.w + c0.w);
    float4 y1 = make_float4(x1.x + c1.x, x1.y + c1.y, x1.z + c1.z, x1.w + c1.w);
    float s  = y0.x + y0.y + y0.z + y0.w + y1.x + y1.y + y1.z + y1.w;
    float s2 = y0.x*y0.x + y0.y*y0.y + y0.z*y0.z + y0.w*y0.w
             + y1.x*y1.x + y1.y*y1.y + y1.z*y1.z + y1.w*y1.w;
    s = warp_sum(s); s2 = warp_sum(s2);
    float mean = s * (1.0f / CDIM);
    float inv  = rsqrtf(s2 * (1.0f / CDIM) - mean * mean + 1e-5f);
    float4 g0 = ((const float4*)g)[lane],  g1 = ((const float4*)g)[lane + 32];
    float4 e0 = ((const float4*)be)[lane], e1 = ((const float4*)be)[lane + 32];
    float4 o0 = make_float4((y0.x - mean) * inv * g0.x + e0.x, (y0.y - mean) * inv * g0.y + e0.y,
                            (y0.z - mean) * inv * g0.z + e0.z, (y0.w - mean) * inv * g0.w + e0.w);
    float4 o1 = make_float4((y1.x - mean) * inv * g1.x + e1.x, (y1.y - mean) * inv * g1.y + e1.y,
                            (y1.z - mean) * inv * g1.z + e1.z, (y1.w - mean) * inv * g1.w + e1.w);
    ((float4*)(out + (size_t)r * CDIM))[lane]      = o0;
    ((float4*)(out + (size_t)r * CDIM))[lane + 32] = o1;
}

// ------------------------- host -------------------------
static void launch_sgemm(const float* A, const float* W, const float* bias,
                         float* C, int M, int Nn, int K, int act)
{
    dim3 grid(Nn / BN, (M + BM - 1) / BM);
    k_sgemm<<<grid, 256>>>(A, W, bias, C, M, Nn, K, act);
}

extern "C" void kernel_launch(void* const* d_in, const int* in_sizes, int n_in,
                              void* d_out, int out_size)
{
    const float* src  = (const float*)d_in[0];
    const float* pos  = (const float*)d_in[1];
    const int*   inds = (const int*)d_in[2];
    const unsigned char* masks = (const unsigned char*)d_in[3];
    const float* ipw = (const float*)d_in[4];
    const float* ipb = (const float*)d_in[5];
    const float* ow  = (const float*)d_in[6];
    const float* ob  = (const float*)d_in[7];
    const float* l1w = (const float*)d_in[8];
    const float* l1b = (const float*)d_in[9];
    const float* l2w = (const float*)d_in[10];
    const float* l2b = (const float*)d_in[11];
    const float* n1g = (const float*)d_in[12];
    const float* n1b = (const float*)d_in[13];
    const float* n2g = (const float*)d_in[14];
    const float* n2b = (const float*)d_in[15];
    const float* eg  = (const float*)d_in[16];
    const float* eb  = (const float*)d_in[17];
    const float* rg  = (const float*)d_in[18];
    const float* rb  = (const float*)d_in[19];
    float* outp = (float*)d_out;

    void* pp; void* pmk;
    cudaGetSymbolAddress(&pp, g_pool);
    cudaGetSymbolAddress(&pmk, g_maskc);
    float* pool = (float*)pp;
    unsigned char* maskc = (unsigned char*)pmk;

    float* qko   = pool;            // 2NC
    float* vproj = pool + 2 * NC;   // 1NC
    float* att   = pool + 3 * NC;   // 1NC
    float* qk    = pool + 4 * NC;   // 1NC (-> proj -> ffo)
    float* proj  = qk;
    float* ffo   = qk;
    float* ffh   = pool;            // 4NC, aliases qko+vproj+att (dead by FF time)
    float* bufA  = pool + 5 * NC;
    float* bufB  = pool + 6 * NC;

    const int attn_smem = 2 * SETSZ * CDIM * (int)sizeof(float);  // 73728 B
    cudaFuncSetAttribute(k_attn, cudaFuncAttributeMaxDynamicSharedMemorySize, attn_smem);

    // canonicalize mask dtype (deterministic)
    k_mask_detect<<<1, 256>>>(masks);
    k_mask_convert<<<(MTOT + 255) / 256, 256>>>(masks);

    const int gather_blocks = NTOT * 64 / 256;   // exact: 65538
    const int ln_blocks     = NTOT / 8;          // exact: 32769

    const float* cur = src;
    int lid = 0;
    for (int blk = 0; blk < 2; blk++) {
        const float* blockin = cur;
        for (int part = 0; part < 2; part++) {
            // shift = blk % 2 == blk (B==2), so (shift,part) and pos(blk,part) share the index
            const int* ind = inds + (size_t)(blk * 2 + part) * NSETS * SETSZ;
            const unsigned char* msk = maskc + (size_t)(blk * 2 + part) * NSETS * SETSZ;
            const float* posl = pos + (size_t)(blk * 2 + part) * NC;

            // 1. gather qk = cur[ind] + pos[ind]
            k_gather_qk<<<gather_blocks, 256>>>(cur, posl, ind, qk);
            // 2. QK in-proj: rows [0, 2C) of in_proj_w  (qk -> qko)
            launch_sgemm(qk, ipw + (size_t)lid * 3 * CDIM * CDIM,
                         ipb + (size_t)lid * 3 * CDIM, qko, NTOT, 2 * CDIM, CDIM, 0);
            // 3. V in-proj straight from cur (voxel order): rows [2C, 3C)
            launch_sgemm(cur, ipw + (size_t)lid * 3 * CDIM * CDIM + 2 * CDIM * CDIM,
                         ipb + (size_t)lid * 3 * CDIM + 2 * CDIM, vproj, NTOT, CDIM, CDIM, 0);
            // 4. attention (V gathered in-kernel via ind)
            k_attn<<<NSETS, 256, attn_smem>>>(qko, vproj, ind, msk, att);
            // 5. out-proj (att -> proj; proj reuses qk slot, qk dead)
            launch_sgemm(att, ow + (size_t)lid * CDIM * CDIM,
                         ob + (size_t)lid * CDIM, proj, NTOT, CDIM, CDIM, 0);
            // 6. scatter + residual + LN1 -> x1 (aliased onto this layer's output buffer)
            float* lout = (part == 0) ? bufA : bufB;
            float* x1 = lout;
            k_scatter_ln<<<ln_blocks, 256>>>(cur, proj, ind,
                                             n1g + (size_t)lid * CDIM, n1b + (size_t)lid * CDIM, x1);
            // 7. FF1 + exact GELU (x1 -> ffh; ffh aliases qko/vproj/att, all dead)
            launch_sgemm(x1, l1w + (size_t)lid * DFFN * CDIM,
                         l1b + (size_t)lid * DFFN, ffh, NTOT, DFFN, CDIM, 1);
            // 8. FF2 (ffh -> ffo; ffo reuses proj slot, proj dead)
            launch_sgemm(ffh, l2w + (size_t)lid * CDIM * DFFN,
                         l2b + (size_t)lid * CDIM, ffo, NTOT, CDIM, DFFN, 0);
            // 9. LN2 + LN3 (in-place on x1/lout; row-wise safe)
            k_ln2_ln3<<<ln_blocks, 256>>>(x1, ffo, cur,
                                          n2g + (size_t)lid * CDIM, n2b + (size_t)lid * CDIM,
                                          eg + (size_t)lid * CDIM,  eb + (size_t)lid * CDIM, lout);
            cur = lout;
            lid++;
        }
        // block residual norm; block-0 output lives in d_out (blockin for block 1).
        // Final iteration reads blockin==d_out and writes d_out in-place (row-wise safe).
        k_add_ln<<<ln_blocks, 256>>>(cur, blockin,
                                     rg + (size_t)blk * CDIM, rb + (size_t)blk * CDIM, outp);
        cur = outp;
    }
}

// round 14
// speedup vs baseline: 1.6923x; 1.6923x over previous
#include <cuda_runtime.h>
#include <cuda_bf16.h>

#define NTOT 262152
#define CDIM 256
#define DFFN 1024
#define NSETS 7282
#define SETSZ 36
#define MTOT (2*2*NSETS*SETSZ)   // 1048608
#define NC   ((size_t)NTOT * CDIM)

// ------------------------- scratch (device globals; no allocation) -------------------------
// Single pool, 7*NC floats = 1.879 GB (inside aarch64 ±4GB reloc window).
//   [0,2NC)   qko   (Q|K after in-proj, set order)      } ffh (N x DFFN = 4NC)
//   [2NC,3NC) vproj (V after in-proj, voxel order)      }  aliases [0,4NC)
//   [3NC,4NC) att   (attention out, set order)          }  after attn+outproj
//   [4NC,5NC) qk -> proj -> ffo (time-multiplexed)
//   [5NC,6NC) bufA  (layer-0 output / x1 alias)
//   [6NC,7NC) bufB  (layer-1 output / x1 alias)
__device__ float g_pool[7 * NC];
__device__ unsigned char g_maskc[MTOT];
__device__ int g_mask_flag;

__device__ __forceinline__ float warp_sum(float v) {
#pragma unroll
    for (int o = 16; o; o >>= 1) v += __shfl_xor_sync(0xffffffffu, v, o);
    return v;
}

// ------------------------- mask dtype detection + canonicalization -------------------------
__global__ void k_mask_detect(const unsigned char* __restrict__ raw) {
    __shared__ unsigned int slo[256], shi[256];
    unsigned int lo = 0, hi = 0;
    for (int i = threadIdx.x; i < 65536; i += 256) {
        unsigned int b = raw[i];
        if ((i & 3) == 0) lo |= b; else hi |= b;
    }
    slo[threadIdx.x] = lo; shi[threadIdx.x] = hi;
    __syncthreads();
    if (threadIdx.x == 0) {
        for (int i = 1; i < 256; i++) { lo |= slo[i]; hi |= shi[i]; }
        int flag;
        if (hi == 0)       flag = 1;   // int32
        else if (lo != 0)  flag = 0;   // uint8
        else               flag = 2;   // float32
        g_mask_flag = flag;
    }
}

__global__ void k_mask_convert(const unsigned char* __restrict__ raw) {
    int i = blockIdx.x * 256 + threadIdx.x;
    if (i >= MTOT) return;
    int f = g_mask_flag;
    unsigned char v;
    if (f == 0)      v = (raw[i] != 0);
    else if (f == 1) v = (((const int*)raw)[i] != 0);
    else             v = (((const float*)raw)[i] != 0.0f);
    g_maskc[i] = v;
}

// ------------------------- gather: qk = x[ind] + pos[ind] (set order) -------------------------
__global__ void __launch_bounds__(256) k_gather_qk(
    const float* __restrict__ x, const float* __restrict__ pos,
    const int* __restrict__ inds, float* __restrict__ qk)
{
    int idx = blockIdx.x * 256 + threadIdx.x;   // NTOT*64 threads exactly
    int r = idx >> 6;
    int c = idx & 63;
    int v = inds[r];
    float4 xv = ((const float4*)x)[(size_t)v * 64 + c];
    float4 pv = ((const float4*)pos)[(size_t)v * 64 + c];
    ((float4*)qk)[(size_t)r * 64 + c] =
        make_float4(xv.x + pv.x, xv.y + pv.y, xv.z + pv.z, xv.w + pv.w);
}

// ============================================================================
// bf16x3 tensor-core GEMM: C = A(MxK) @ W(NnxK)^T + bias, optional exact GELU
// Each fp32 value x is split once (at SMEM load) into hi=bf16(x), lo=bf16(x-hi).
// Product accumulated as hi*hi + hi*lo + lo*hi in fp32 via mma.m16n8k16.
// Block tile 128x128x32; 8 warps of 32(m)x64(n); SMEM row stride 40 bf16.
// ============================================================================
#define BM 128
#define BN 128
#define BK 32
#define KW 20   // SMEM row stride in 32-bit words (= 40 bf16)

__device__ __forceinline__ unsigned pack2(__nv_bfloat16 a, __nv_bfloat16 b) {
    __nv_bfloat162 t; t.x = a; t.y = b;
    return *reinterpret_cast<unsigned*>(&t);
}

__device__ __forceinline__ void mma16816(float* c, const unsigned* a, const unsigned* b) {
    asm volatile(
        "mma.sync.aligned.m16n8k16.row.col.f32.bf16.bf16.f32 "
        "{%0,%1,%2,%3}, {%4,%5,%6,%7}, {%8,%9}, {%0,%1,%2,%3};\n"
        : "+f"(c[0]), "+f"(c[1]), "+f"(c[2]), "+f"(c[3])
        : "r"(a[0]), "r"(a[1]), "r"(a[2]), "r"(a[3]), "r"(b[0]), "r"(b[1]));
}

// load a 128x32 fp32 tile (row-major, leading dim ld) and store split hi/lo bf16
// thread t: row = t>>1, k-halves of 16 floats selected by t&1
__device__ __forceinline__ void load_split_tile(
    const float* __restrict__ src, int ld, int row_limit, int grow0, int k0,
    unsigned* __restrict__ shi, unsigned* __restrict__ slo, int tid)
{
    int r     = tid >> 1;
    int kbase = (tid & 1) * 16;
    int grow  = grow0 + r;
    bool ok   = grow < row_limit;
    const float* p = src + (size_t)grow * ld + k0 + kbase;
    int wbase = r * KW + (kbase >> 1);
#pragma unroll
    for (int q = 0; q < 4; q++) {
        float4 v = ok ? *(const float4*)(p + q * 4) : make_float4(0.f, 0.f, 0.f, 0.f);
        __nv_bfloat16 h0 = __float2bfloat16(v.x), h1 = __float2bfloat16(v.y),
                      h2 = __float2bfloat16(v.z), h3 = __float2bfloat16(v.w);
        float l0 = v.x - __bfloat162float(h0), l1 = v.y - __bfloat162float(h1),
              l2 = v.z - __bfloat162float(h2), l3 = v.w - __bfloat162float(h3);
        uint2 hv = make_uint2(pack2(h0, h1), pack2(h2, h3));
        uint2 lv = make_uint2(pack2(__float2bfloat16(l0), __float2bfloat16(l1)),
                              pack2(__float2bfloat16(l2), __float2bfloat16(l3)));
        *(uint2*)(shi + wbase + q * 2) = hv;
        *(uint2*)(slo + wbase + q * 2) = lv;
    }
}

__device__ __forceinline__ float gelu_exact(float x) {
    return 0.5f * x * (1.0f + erff(x * 0.70710678118654752f));
}

__global__ void __launch_bounds__(256, 2) k_mma_gemm(
    const float* __restrict__ A, const float* __restrict__ W,
    const float* __restrict__ bias, float* __restrict__ C,
    int M, int Nn, int K, int act)
{
    extern __shared__ __align__(16) unsigned smem[];
    unsigned* sAhi = smem;                 // 128*20 words
    unsigned* sAlo = smem + BM * KW;
    unsigned* sBhi = smem + 2 * BM * KW;
    unsigned* sBlo = smem + 3 * BM * KW;   // total 10240 words = 40 KB

    int tid  = threadIdx.x;
    int lane = tid & 31;
    int wid  = tid >> 5;
    int wm   = wid & 3;    // row band: 32 rows each
    int wn   = wid >> 2;   // col band: 64 cols each
    int row0 = blockIdx.y * BM;
    int col0 = blockIdx.x * BN;
    int g    = lane >> 2;
    int l3   = lane & 3;

    float acc[2][8][4];
#pragma unroll
    for (int mt = 0; mt < 2; mt++)
#pragma unroll
        for (int nt = 0; nt < 8; nt++)
#pragma unroll
            for (int e = 0; e < 4; e++) acc[mt][nt][e] = 0.f;

    // per-thread fragment base indices (word units)
    int rA[2][2], rB[8];
#pragma unroll
    for (int mt = 0; mt < 2; mt++) {
        int r = wm * 32 + mt * 16 + g;
        rA[mt][0] = r * KW + l3;
        rA[mt][1] = (r + 8) * KW + l3;
    }
#pragma unroll
    for (int nt = 0; nt < 8; nt++) {
        int n = wn * 64 + nt * 8 + g;
        rB[nt] = n * KW + l3;
    }

    for (int k0 = 0; k0 < K; k0 += BK) {
        __syncthreads();   // previous compute done before SMEM overwrite
        load_split_tile(A, K, M,          row0, k0, sAhi, sAlo, tid);
        load_split_tile(W, K, 0x7fffffff, col0, k0, sBhi, sBlo, tid);
        __syncthreads();

#pragma unroll
        for (int s = 0; s < 2; s++) {
            int ks = s * 8;
            unsigned ah[2][4], al[2][4];
#pragma unroll
            for (int mt = 0; mt < 2; mt++) {
                ah[mt][0] = sAhi[rA[mt][0] + ks];
                ah[mt][1] = sAhi[rA[mt][1] + ks];
                ah[mt][2] = sAhi[rA[mt][0] + ks + 4];
                ah[mt][3] = sAhi[rA[mt][1] + ks + 4];
                al[mt][0] = sAlo[rA[mt][0] + ks];
                al[mt][1] = sAlo[rA[mt][1] + ks];
                al[mt][2] = sAlo[rA[mt][0] + ks + 4];
                al[mt][3] = sAlo[rA[mt][1] + ks + 4];
            }
#pragma unroll
            for (int half = 0; half < 2; half++) {
                unsigned bh[4][2], bl[4][2];
#pragma unroll
                for (int j = 0; j < 4; j++) {
                    int nt = half * 4 + j;
                    bh[j][0] = sBhi[rB[nt] + ks];
                    bh[j][1] = sBhi[rB[nt] + ks + 4];
                    bl[j][0] = sBlo[rB[nt] + ks];
                    bl[j][1] = sBlo[rB[nt] + ks + 4];
                }
#pragma unroll
                for (int mt = 0; mt < 2; mt++)
#pragma unroll
                    for (int j = 0; j < 4; j++) {
                        float* c = acc[mt][half * 4 + j];
                        mma16816(c, ah[mt], bh[j]);   // hi*hi
                        mma16816(c, ah[mt], bl[j]);   // hi*lo
                        mma16816(c, al[mt], bh[j]);   // lo*hi
                    }
            }
        }
    }

    // epilogue: bias + optional exact GELU, float2 stores
#pragma unroll
    for (int mt = 0; mt < 2; mt++) {
        int rlo = row0 + wm * 32 + mt * 16 + g;
        int rhi = rlo + 8;
#pragma unroll
        for (int nt = 0; nt < 8; nt++) {
            int cn = col0 + wn * 64 + nt * 8 + l3 * 2;
            float2 bb = *(const float2*)(bias + cn);
            float* c = acc[mt][nt];
            if (rlo < M) {
                float x0 = c[0] + bb.x, x1 = c[1] + bb.y;
                if (act) { x0 = gelu_exact(x0); x1 = gelu_exact(x1); }
                *(float2*)(C + (size_t)rlo * Nn + cn) = make_float2(x0, x1);
            }
            if (rhi < M) {
                float x2 = c[2] + bb.x, x3 = c[3] + bb.y;
                if (act) { x2 = gelu_exact(x2); x3 = gelu_exact(x3); }
                *(float2*)(C + (size_t)rhi * Nn + cn) = make_float2(x2, x3);
            }
        }
    }
}

// ------------------------- per-set masked MHA -------------------------
__global__ void __launch_bounds__(256) k_attn(
    const float* __restrict__ qko,    // N x 512 : [0:256)=Q, [256:512)=K (set order)
    const float* __restrict__ vproj,  // N x 256 (voxel order)
    const int* __restrict__ inds,
    const unsigned char* __restrict__ mask,
    float* __restrict__ out)          // N x 256 (set order)
{
    extern __shared__ float sm[];
    float* Ks = sm;                  // 36*256
    float* Vs = sm + SETSZ * CDIM;   // 36*256
    __shared__ unsigned char ms[SETSZ];
    __shared__ int vind[SETSZ];

    int s   = blockIdx.x;
    int tid = threadIdx.x;
    size_t base = (size_t)s * SETSZ;

    if (tid < SETSZ) { ms[tid] = mask[base + tid]; vind[tid] = inds[base + tid]; }
    __syncthreads();

    for (int i = tid; i < SETSZ * 64; i += 256) {
        int m = i >> 6, c = i & 63;
        ((float4*)Ks)[(size_t)m * 64 + c] = *((const float4*)(qko + (base + m) * 512 + 256) + c);
        ((float4*)Vs)[(size_t)m * 64 + c] = ((const float4*)vproj)[(size_t)vind[m] * 64 + c];
    }
    __syncthreads();

    for (int pair = tid; pair < SETSZ * 8; pair += 256) {
        int h = pair / SETSZ;
        int l = pair % SETSZ;

        const float* qp = qko + (base + l) * 512 + h * 32;
        float q[32];
#pragma unroll
        for (int d = 0; d < 32; d += 4) {
            float4 t = *(const float4*)(qp + d);
            q[d] = t.x; q[d + 1] = t.y; q[d + 2] = t.z; q[d + 3] = t.w;
        }

        float sc[SETSZ];
        float mx = -1e30f;
#pragma unroll
        for (int m = 0; m < SETSZ; m++) {
            const float* kp = Ks + m * CDIM + h * 32;
            float a = 0.f;
#pragma unroll
            for (int d = 0; d < 32; d++) a += q[d] * kp[d];
            a *= 0.17677669529663687f;          // 1/sqrt(32)
            if (ms[m]) a = -1e30f;
            sc[m] = a;
            mx = fmaxf(mx, a);
        }
        float den = 0.f;
#pragma unroll
        for (int m = 0; m < SETSZ; m++) {
            float e = ms[m] ? 0.f : __expf(sc[m] - mx);
            sc[m] = e;
            den += e;
        }
        float inv = 1.0f / den;

        float o[32];
#pragma unroll
        for (int d = 0; d < 32; d++) o[d] = 0.f;
#pragma unroll
        for (int m = 0; m < SETSZ; m++) {
            float a = sc[m] * inv;
            const float* vp = Vs + m * CDIM + h * 32;
#pragma unroll
            for (int d = 0; d < 32; d++) o[d] += a * vp[d];
        }
        float* op = out + (base + l) * 256 + h * 32;
#pragma unroll
        for (int d = 0; d < 32; d += 4)
            *(float4*)(op + d) = make_float4(o[d], o[d + 1], o[d + 2], o[d + 3]);
    }
}

// ------------------------- scatter + residual + LN1 (warp per set-row) -------------------------
__global__ void __launch_bounds__(256) k_scatter_ln(
    const float* __restrict__ xin, const float* __restrict__ proj,
    const int* __restrict__ inds, const float* __restrict__ gam,
    const float* __restrict__ bet, float* __restrict__ out)
{
    int r = (blockIdx.x * 256 + threadIdx.x) >> 5;
    int lane = threadIdx.x & 31;
    int v = inds[r];
    const float4* x4 = (const float4*)(xin + (size_t)v * CDIM);
    const float4* p4 = (const float4*)(proj + (size_t)r * CDIM);
    float4 a0 = x4[lane],      b0 = p4[lane];
    float4 a1 = x4[lane + 32], b1 = p4[lane + 32];
    float4 y0 = make_float4(a0.x + b0.x, a0.y + b0.y, a0.z + b0.z, a0.w + b0.w);
    float4 y1 = make_float4(a1.x + b1.x, a1.y + b1.y, a1.z + b1.z, a1.w + b1.w);
    float s  = y0.x + y0.y + y0.z + y0.w + y1.x + y1.y + y1.z + y1.w;
    float s2 = y0.x*y0.x + y0.y*y0.y + y0.z*y0.z + y0.w*y0.w
             + y1.x*y1.x + y1.y*y1.y + y1.z*y1.z + y1.w*y1.w;
    s = warp_sum(s); s2 = warp_sum(s2);
    float mean = s * (1.0f / CDIM);
    float inv  = rsqrtf(s2 * (1.0f / CDIM) - mean * mean + 1e-5f);
    float4 g0 = ((const float4*)gam)[lane],      g1 = ((const float4*)gam)[lane + 32];
    float4 c0 = ((const float4*)bet)[lane],      c1 = ((const float4*)bet)[lane + 32];
    float4 o0 = make_float4((y0.x - mean) * inv * g0.x + c0.x, (y0.y - mean) * inv * g0.y + c0.y,
                            (y0.z - mean) * inv * g0.z + c0.z, (y0.w - mean) * inv * g0.w + c0.w);
    float4 o1 = make_float4((y1.x - mean) * inv * g1.x + c1.x, (y1.y - mean) * inv * g1.y + c1.y,
                            (y1.z - mean) * inv * g1.z + c1.z, (y1.w - mean) * inv * g1.w + c1.w);
    ((float4*)(out + (size_t)v * CDIM))[lane]      = o0;
    ((float4*)(out + (size_t)v * CDIM))[lane + 32] = o1;
}

// ------------------------- LN2 then LN3 fused (warp per voxel row) -------------------------
__global__ void __launch_bounds__(256) k_ln2_ln3(
    const float* x1, const float* __restrict__ ff,
    const float* __restrict__ idn,
    const float* __restrict__ g2, const float* __restrict__ b2,
    const float* __restrict__ g3, const float* __restrict__ b3,
    float* out)
{
    int r = (blockIdx.x * 256 + threadIdx.x) >> 5;
    int lane = threadIdx.x & 31;
    const float4* a4 = (const float4*)(x1 + (size_t)r * CDIM);
    const float4* f4 = (const float4*)(ff + (size_t)r * CDIM);
    float4 a0 = a4[lane],      c0 = f4[lane];
    float4 a1 = a4[lane + 32], c1 = f4[lane + 32];
    float4 y0 = make_float4(a0.x + c0.x, a0.y + c0.y, a0.z + c0.z, a0.w + c0.w);
    float4 y1 = make_float4(a1.x + c1.x, a1.y + c1.y, a1.z + c1.z, a1.w + c1.w);
    float s  = y0.x + y0.y + y0.z + y0.w + y1.x + y1.y + y1.z + y1.w;
    float s2 = y0.x*y0.x + y0.y*y0.y + y0.z*y0.z + y0.w*y0.w
             + y1.x*y1.x + y1.y*y1.y + y1.z*y1.z + y1.w*y1.w;
    s = warp_sum(s); s2 = warp_sum(s2);
    float mean = s * (1.0f / CDIM);
    float inv  = rsqrtf(s2 * (1.0f / CDIM) - mean * mean + 1e-5f);
    float4 g20 = ((const float4*)g2)[lane],      g21 = ((const float4*)g2)[lane + 32];
    float4 b20 = ((const float4*)b2)[lane],      b21 = ((const float4*)b2)[lane + 32];
    const float4* i4 = (const float4*)(idn + (size_t)r * CDIM);
    float4 i0 = i4[lane], i1 = i4[lane + 32];
    float4 z0 = make_float4((y0.x - mean) * inv * g20.x + b20.x + i0.x,
                            (y0.y - mean) * inv * g20.y + b20.y + i0.y,
                            (y0.z - mean) * inv * g20.z + b20.z + i0.z,
                            (y0.w - mean) * inv * g20.w + b20.w + i0.w);
    float4 z1 = make_float4((y1.x - mean) * inv * g21.x + b21.x + i1.x,
                            (y1.y - mean) * inv * g21.y + b21.y + i1.y,
                            (y1.z - mean) * inv * g21.z + b21.z + i1.z,
                            (y1.w - mean) * inv * g21.w + b21.w + i1.w);
    float t  = z0.x + z0.y + z0.z + z0.w + z1.x + z1.y + z1.z + z1.w;
    float t2 = z0.x*z0.x + z0.y*z0.y + z0.z*z0.z + z0.w*z0.w
             + z1.x*z1.x + z1.y*z1.y + z1.z*z1.z + z1.w*z1.w;
    t = warp_sum(t); t2 = warp_sum(t2);
    float mean2 = t * (1.0f / CDIM);
    float inv2  = rsqrtf(t2 * (1.0f / CDIM) - mean2 * mean2 + 1e-5f);
    float4 g30 = ((const float4*)g3)[lane],      g31 = ((const float4*)g3)[lane + 32];
    float4 b30 = ((const float4*)b3)[lane],      b31 = ((const float4*)b3)[lane + 32];
    float4 o0 = make_float4((z0.x - mean2) * inv2 * g30.x + b30.x, (z0.y - mean2) * inv2 * g30.y + b30.y,
                            (z0.z - mean2) * inv2 * g30.z + b30.z, (z0.w - mean2) * inv2 * g30.w + b30.w);
    float4 o1 = make_float4((z1.x - mean2) * inv2 * g31.x + b31.x, (z1.y - mean2) * inv2 * g31.y + b31.y,
                            (z1.z - mean2) * inv2 * g31.z + b31.z, (z1.w - mean2) * inv2 * g31.w + b31.w);
    ((float4*)(out + (size_t)r * CDIM))[lane]      = o0;
    ((float4*)(out + (size_t)r * CDIM))[lane + 32] = o1;
}

// ------------------------- block-end: LN(a + b) -------------------------
__global__ void __launch_bounds__(256) k_add_ln(
    const float* __restrict__ a, const float* b,
    const float* __restrict__ g, const float* __restrict__ be,
    float* out)
{
    int r = (blockIdx.x * 256 + threadIdx.x) >> 5;
    int lane = threadIdx.x & 31;
    const float4* a4 = (const float4*)(a + (size_t)r * CDIM);
    const float4* b4 = (const float4*)(b + (size_t)r * CDIM);
    float4 x0 = a4[lane],      x1 = a4[lane + 32];
    float4 c0 = b4[lane],      c1 = b4[lane + 32];
    float4 y0 = make_float4(x0.x + c0.x, x0.y + c0.y, x0.z + c0.z, x0.w + c0.w);
    float4 y1 = make_float4(x1.x + c1.x, x1.y + c1.y, x1.z + c1.z, x1.w + c1.w);
    float s  = y0.x + y0.y + y0.z + y0.w + y1.x + y1.y + y1.z + y1.w;
    float s2 = y0.x*y0.x + y0.y*y0.y + y0.z*y0.z + y0.w*y0.w
             + y1.x*y1.x + y1.y*y1.y + y1.z*y1.z + y1.w*y1.w;
    s = warp_sum(s); s2 = warp_sum(s2);
    float mean = s * (1.0f / CDIM);
    float inv  = rsqrtf(s2 * (1.0f / CDIM) - mean * mean + 1e-5f);
    float4 g0 = ((const float4*)g)[lane],  g1 = ((const float4*)g)[lane + 32];
    float4 e0 = ((const float4*)be)[lane], e1 = ((const float4*)be)[lane + 32];
    float4 o0 = make_float4((y0.x - mean) * inv * g0.x + e0.x, (y0.y - mean) * inv * g0.y + e0.y,
                            (y0.z - mean) * inv * g0.z + e0.z, (y0.w - mean) * inv * g0.w + e0.w);
    float4 o1 = make_float4((y1.x - mean) * inv * g1.x + e1.x, (y1.y - mean) * inv * g1.y + e1.y,
                            (y1.z - mean) * inv * g1.z + e1.z, (y1.w - mean) * inv * g1.w + e1.w);
    ((float4*)(out + (size_t)r * CDIM))[lane]      = o0;
    ((float4*)(out + (size_t)r * CDIM))[lane + 32] = o1;
}

// ------------------------- host -------------------------
#define GEMM_SMEM (4 * BM * KW * 4)   // 40960 bytes

static void launch_gemm(const float* A, const float* W, const float* bias,
                        float* C, int M, int Nn, int K, int act)
{
    dim3 grid(Nn / BN, (M + BM - 1) / BM);
    k_mma_gemm<<<grid, 256, GEMM_SMEM>>>(A, W, bias, C, M, Nn, K, act);
}

extern "C" void kernel_launch(void* const* d_in, const int* in_sizes, int n_in,
                              void* d_out, int out_size)
{
    const float* src  = (const float*)d_in[0];
    const float* pos  = (const float*)d_in[1];
    const int*   inds = (const int*)d_in[2];
    const unsigned char* masks = (const unsigned char*)d_in[3];
    const float* ipw = (const float*)d_in[4];
    const float* ipb = (const float*)d_in[5];
    const float* ow  = (const float*)d_in[6];
    const float* ob  = (const float*)d_in[7];
    const float* l1w = (const float*)d_in[8];
    const float* l1b = (const float*)d_in[9];
    const float* l2w = (const float*)d_in[10];
    const float* l2b = (const float*)d_in[11];
    const float* n1g = (const float*)d_in[12];
    const float* n1b = (const float*)d_in[13];
    const float* n2g = (const float*)d_in[14];
    const float* n2b = (const float*)d_in[15];
    const float* eg  = (const float*)d_in[16];
    const float* eb  = (const float*)d_in[17];
    const float* rg  = (const float*)d_in[18];
    const float* rb  = (const float*)d_in[19];
    float* outp = (float*)d_out;

    void* pp; void* pmk;
    cudaGetSymbolAddress(&pp, g_pool);
    cudaGetSymbolAddress(&pmk, g_maskc);
    float* pool = (float*)pp;
    unsigned char* maskc = (unsigned char*)pmk;

    float* qko   = pool;            // 2NC
    float* vproj = pool + 2 * NC;   // 1NC
    float* att   = pool + 3 * NC;   // 1NC
    float* qk    = pool + 4 * NC;   // 1NC (-> proj -> ffo)
    float* proj  = qk;
    float* ffo   = qk;
    float* ffh   = pool;            // 4NC, aliases qko+vproj+att (dead by FF time)
    float* bufA  = pool + 5 * NC;
    float* bufB  = pool + 6 * NC;

    const int attn_smem = 2 * SETSZ * CDIM * (int)sizeof(float);  // 73728 B
    cudaFuncSetAttribute(k_attn, cudaFuncAttributeMaxDynamicSharedMemorySize, attn_smem);

    k_mask_detect<<<1, 256>>>(masks);
    k_mask_convert<<<(MTOT + 255) / 256, 256>>>(masks);

    const int gather_blocks = NTOT * 64 / 256;   // 65538
    const int ln_blocks     = NTOT / 8;          // 32769

    const float* cur = src;
    int lid = 0;
    for (int blk = 0; blk < 2; blk++) {
        const float* blockin = cur;
        for (int part = 0; part < 2; part++) {
            const int* ind = inds + (size_t)(blk * 2 + part) * NSETS * SETSZ;
            const unsigned char* msk = maskc + (size_t)(blk * 2 + part) * NSETS * SETSZ;
            const float* posl = pos + (size_t)(blk * 2 + part) * NC;

            k_gather_qk<<<gather_blocks, 256>>>(cur, posl, ind, qk);
            launch_gemm(qk, ipw + (size_t)lid * 3 * CDIM * CDIM,
                        ipb + (size_t)lid * 3 * CDIM, qko, NTOT, 2 * CDIM, CDIM, 0);
            launch_gemm(cur, ipw + (size_t)lid * 3 * CDIM * CDIM + 2 * CDIM * CDIM,
                        ipb + (size_t)lid * 3 * CDIM + 2 * CDIM, vproj, NTOT, CDIM, CDIM, 0);
            k_attn<<<NSETS, 256, attn_smem>>>(qko, vproj, ind, msk, att);
            launch_gemm(att, ow + (size_t)lid * CDIM * CDIM,
                        ob + (size_t)lid * CDIM, proj, NTOT, CDIM, CDIM, 0);
            float* lout = (part == 0) ? bufA : bufB;
            float* x1 = lout;
            k_scatter_ln<<<ln_blocks, 256>>>(cur, proj, ind,
                                             n1g + (size_t)lid * CDIM, n1b + (size_t)lid * CDIM, x1);
            launch_gemm(x1, l1w + (size_t)lid * DFFN * CDIM,
                        l1b + (size_t)lid * DFFN, ffh, NTOT, DFFN, CDIM, 1);
            launch_gemm(ffh, l2w + (size_t)lid * CDIM * DFFN,
                        l2b + (size_t)lid * CDIM, ffo, NTOT, CDIM, DFFN, 0);
            k_ln2_ln3<<<ln_blocks, 256>>>(x1, ffo, cur,
                                          n2g + (size_t)lid * CDIM, n2b + (size_t)lid * CDIM,
                                          eg + (size_t)lid * CDIM,  eb + (size_t)lid * CDIM, lout);
            cur = lout;
            lid++;
        }
        k_add_ln<<<ln_blocks, 256>>>(cur, blockin,
                                     rg + (size_t)blk * CDIM, rb + (size_t)blk * CDIM, outp);
        cur = outp;
    }
}

// round 15
// speedup vs baseline: 1.9314x; 1.1413x over previous
#include <cuda_runtime.h>
#include <cuda_bf16.h>

#define NTOT 262152
#define CDIM 256
#define DFFN 1024
#define NSETS 7282
#define SETSZ 36
#define MTOT (2*2*NSETS*SETSZ)   // 1048608
#define NC   ((size_t)NTOT * CDIM)

// ------------------------- scratch (device globals; no allocation) -------------------------
// Single pool, 7*NC floats = 1.879 GB (inside aarch64 ±4GB reloc window).
//   [0,2NC)   qko   (Q|K after in-proj, set order)      } ffh (N x DFFN = 4NC)
//   [2NC,3NC) vproj (V after in-proj, voxel order)      }  aliases [0,4NC)
//   [3NC,4NC) att   (attention out, set order)          }  after attn+outproj
//   [4NC,5NC) qk -> proj -> ffo (time-multiplexed)
//   [5NC,6NC) bufA  (layer-0 output / x1 alias)
//   [6NC,7NC) bufB  (layer-1 output / x1 alias)
__device__ float g_pool[7 * NC];
__device__ unsigned char g_maskc[MTOT];
__device__ int g_mask_flag;

__device__ __forceinline__ float warp_sum(float v) {
#pragma unroll
    for (int o = 16; o; o >>= 1) v += __shfl_xor_sync(0xffffffffu, v, o);
    return v;
}

// ------------------------- mask dtype detection + canonicalization -------------------------
__global__ void k_mask_detect(const unsigned char* __restrict__ raw) {
    __shared__ unsigned int slo[256], shi[256];
    unsigned int lo = 0, hi = 0;
    for (int i = threadIdx.x; i < 65536; i += 256) {
        unsigned int b = raw[i];
        if ((i & 3) == 0) lo |= b; else hi |= b;
    }
    slo[threadIdx.x] = lo; shi[threadIdx.x] = hi;
    __syncthreads();
    if (threadIdx.x == 0) {
        for (int i = 1; i < 256; i++) { lo |= slo[i]; hi |= shi[i]; }
        int flag;
        if (hi == 0)       flag = 1;   // int32
        else if (lo != 0)  flag = 0;   // uint8
        else               flag = 2;   // float32
        g_mask_flag = flag;
    }
}

__global__ void k_mask_convert(const unsigned char* __restrict__ raw) {
    int i = blockIdx.x * 256 + threadIdx.x;
    if (i >= MTOT) return;
    int f = g_mask_flag;
    unsigned char v;
    if (f == 0)      v = (raw[i] != 0);
    else if (f == 1) v = (((const int*)raw)[i] != 0);
    else             v = (((const float*)raw)[i] != 0.0f);
    g_maskc[i] = v;
}

// ------------------------- gather: qk = x[ind] + pos[ind] (set order) -------------------------
__global__ void __launch_bounds__(256) k_gather_qk(
    const float* __restrict__ x, const float* __restrict__ pos,
    const int* __restrict__ inds, float* __restrict__ qk)
{
    int idx = blockIdx.x * 256 + threadIdx.x;   // NTOT*64 threads exactly
    int r = idx >> 6;
    int c = idx & 63;
    int v = inds[r];
    float4 xv = ((const float4*)x)[(size_t)v * 64 + c];
    float4 pv = ((const float4*)pos)[(size_t)v * 64 + c];
    ((float4*)qk)[(size_t)r * 64 + c] =
        make_float4(xv.x + pv.x, xv.y + pv.y, xv.z + pv.z, xv.w + pv.w);
}

// ============================================================================
// bf16x3 tensor-core GEMM v2: C = A(MxK) @ W(NnxK)^T + bias, optional GELU
// fp32 tiles staged in SMEM via 2-stage cp.async; hi/lo bf16 split happens at
// fragment-load time (one LDS.64 -> both hi & lo fragments).
// CTA tile 256x128x32; 8 warps as 4(m)x2(n), warp tile 64x64.
// SMEM row stride 40 words -> conflict-free LDS.64 frags & cp.async stores.
// ============================================================================
#define GBM 256
#define GBN 128
#define GBK 32
#define AKW 40                              // fp32 words per SMEM row (32 + 8 pad)
#define A_WORDS (GBM * AKW)                 // 10240
#define B_WORDS (GBN * AKW)                 // 5120
#define STAGE_WORDS (A_WORDS + B_WORDS)     // 15360
#define GEMM_SMEM (2 * STAGE_WORDS * 4)     // 122880 bytes

__device__ __forceinline__ void mma16816(float* c, const unsigned* a, const unsigned* b) {
    asm volatile(
        "mma.sync.aligned.m16n8k16.row.col.f32.bf16.bf16.f32 "
        "{%0,%1,%2,%3}, {%4,%5,%6,%7}, {%8,%9}, {%0,%1,%2,%3};\n"
        : "+f"(c[0]), "+f"(c[1]), "+f"(c[2]), "+f"(c[3])
        : "r"(a[0]), "r"(a[1]), "r"(a[2]), "r"(a[3]), "r"(b[0]), "r"(b[1]));
}

__device__ __forceinline__ void split2(float2 v, unsigned& hi, unsigned& lo) {
    __nv_bfloat162 h2 = __float22bfloat162_rn(v);
    float2 hf = __bfloat1622float2(h2);
    __nv_bfloat162 l2 = __float22bfloat162_rn(make_float2(v.x - hf.x, v.y - hf.y));
    hi = *reinterpret_cast<unsigned*>(&h2);
    lo = *reinterpret_cast<unsigned*>(&l2);
}

__device__ __forceinline__ float gelu_exact(float x) {
    return 0.5f * x * (1.0f + erff(x * 0.70710678118654752f));
}

__global__ void __launch_bounds__(256, 1) k_mma_gemm(
    const float* __restrict__ A, const float* __restrict__ W,
    const float* __restrict__ bias, float* __restrict__ C,
    int M, int Nn, int K, int act)
{
    extern __shared__ __align__(16) float smem[];
    int tid  = threadIdx.x;
    int lane = tid & 31;
    int wid  = tid >> 5;
    int wm   = wid >> 1;    // 0..3  (64-row band)
    int wn   = wid & 1;     // 0..1  (64-col band)
    int row0 = blockIdx.y * GBM;
    int col0 = blockIdx.x * GBN;
    int g    = lane >> 2;
    int l3   = lane & 3;

    unsigned sbase = (unsigned)__cvta_generic_to_shared(smem);

    float acc[4][8][4];
#pragma unroll
    for (int mt = 0; mt < 4; mt++)
#pragma unroll
        for (int nt = 0; nt < 8; nt++)
#pragma unroll
            for (int e = 0; e < 4; e++) acc[mt][nt][e] = 0.f;

    // loader mapping: 8 lanes per row (16B each), 32 rows per pass
    int lrr = tid >> 3;          // 0..31
    int lcc = (tid & 7) * 4;     // float offset

    auto load_stage = [&](int st, int k0) {
        unsigned sA = sbase + (unsigned)(st * STAGE_WORDS) * 4u;
        unsigned sB = sA + A_WORDS * 4u;
        const float* Ap = A + (size_t)(row0 + lrr) * K + k0 + lcc;
        unsigned sa = sA + (unsigned)(lrr * AKW + lcc) * 4u;
#pragma unroll
        for (int p = 0; p < 8; p++) {
            int grow = row0 + p * 32 + lrr;
            int sz = (grow < M) ? 16 : 0;
            asm volatile("cp.async.cg.shared.global [%0], [%1], 16, %2;\n"
                :: "r"(sa + (unsigned)(p * 32 * AKW) * 4u),
                   "l"(Ap + (size_t)p * 32 * K), "r"(sz));
        }
        const float* Wp = W + (size_t)(col0 + lrr) * K + k0 + lcc;
        unsigned sb = sB + (unsigned)(lrr * AKW + lcc) * 4u;
#pragma unroll
        for (int p = 0; p < 4; p++) {
            asm volatile("cp.async.cg.shared.global [%0], [%1], 16;\n"
                :: "r"(sb + (unsigned)(p * 32 * AKW) * 4u),
                   "l"(Wp + (size_t)p * 32 * K));
        }
        asm volatile("cp.async.commit_group;\n");
    };

    auto compute_stage = [&](int st) {
        const float* sA = smem + st * STAGE_WORDS;
        const float* sB = sA + A_WORDS;
#pragma unroll
        for (int half = 0; half < 2; half++) {
            int ks = half * 16 + 2 * l3;
            unsigned ah[4][4], al[4][4];
#pragma unroll
            for (int mt = 0; mt < 4; mt++) {
                int r = wm * 64 + mt * 16 + g;
#pragma unroll
                for (int q = 0; q < 4; q++) {
                    int rr = r + (q & 1) * 8;
                    int kk = ks + (q >> 1) * 8;
                    float2 v = *(const float2*)(sA + rr * AKW + kk);
                    split2(v, ah[mt][q], al[mt][q]);
                }
            }
#pragma unroll
            for (int nt = 0; nt < 8; nt++) {
                int n = wn * 64 + nt * 8 + g;
                unsigned bh[2], bl[2];
#pragma unroll
                for (int q = 0; q < 2; q++) {
                    float2 v = *(const float2*)(sB + n * AKW + ks + q * 8);
                    split2(v, bh[q], bl[q]);
                }
#pragma unroll
                for (int mt = 0; mt < 4; mt++) {
                    float* c = acc[mt][nt];
                    mma16816(c, ah[mt], bh);   // hi*hi
                    mma16816(c, ah[mt], bl);   // hi*lo
                    mma16816(c, al[mt], bh);   // lo*hi
                }
            }
        }
    };

    int T = K / GBK;
    load_stage(0, 0);
    int st = 0;
    for (int t = 0; t < T; t++) {
        if (t + 1 < T) {
            load_stage(st ^ 1, (t + 1) * GBK);
            asm volatile("cp.async.wait_group 1;\n");
        } else {
            asm volatile("cp.async.wait_group 0;\n");
        }
        __syncthreads();
        compute_stage(st);
        __syncthreads();
        st ^= 1;
    }

    // epilogue: bias + optional exact GELU, float2 stores
#pragma unroll
    for (int mt = 0; mt < 4; mt++) {
        int rlo = row0 + wm * 64 + mt * 16 + g;
        int rhi = rlo + 8;
#pragma unroll
        for (int nt = 0; nt < 8; nt++) {
            int cn = col0 + wn * 64 + nt * 8 + 2 * l3;
            float2 bb = *(const float2*)(bias + cn);
            float* c = acc[mt][nt];
            if (rlo < M) {
                float x0 = c[0] + bb.x, x1 = c[1] + bb.y;
                if (act) { x0 = gelu_exact(x0); x1 = gelu_exact(x1); }
                *(float2*)(C + (size_t)rlo * Nn + cn) = make_float2(x0, x1);
            }
            if (rhi < M) {
                float x2 = c[2] + bb.x, x3 = c[3] + bb.y;
                if (act) { x2 = gelu_exact(x2); x3 = gelu_exact(x3); }
                *(float2*)(C + (size_t)rhi * Nn + cn) = make_float2(x2, x3);
            }
        }
    }
}

// ------------------------- per-set masked MHA -------------------------
__global__ void __launch_bounds__(256) k_attn(
    const float* __restrict__ qko,    // N x 512 : [0:256)=Q, [256:512)=K (set order)
    const float* __restrict__ vproj,  // N x 256 (voxel order)
    const int* __restrict__ inds,
    const unsigned char* __restrict__ mask,
    float* __restrict__ out)          // N x 256 (set order)
{
    extern __shared__ float sm[];
    float* Ks = sm;                  // 36*256
    float* Vs = sm + SETSZ * CDIM;   // 36*256
    __shared__ unsigned char ms[SETSZ];
    __shared__ int vind[SETSZ];

    int s   = blockIdx.x;
    int tid = threadIdx.x;
    size_t base = (size_t)s * SETSZ;

    if (tid < SETSZ) { ms[tid] = mask[base + tid]; vind[tid] = inds[base + tid]; }
    __syncthreads();

    for (int i = tid; i < SETSZ * 64; i += 256) {
        int m = i >> 6, c = i & 63;
        ((float4*)Ks)[(size_t)m * 64 + c] = *((const float4*)(qko + (base + m) * 512 + 256) + c);
        ((float4*)Vs)[(size_t)m * 64 + c] = ((const float4*)vproj)[(size_t)vind[m] * 64 + c];
    }
    __syncthreads();

    for (int pair = tid; pair < SETSZ * 8; pair += 256) {
        int h = pair / SETSZ;
        int l = pair % SETSZ;

        const float* qp = qko + (base + l) * 512 + h * 32;
        float q[32];
#pragma unroll
        for (int d = 0; d < 32; d += 4) {
            float4 t = *(const float4*)(qp + d);
            q[d] = t.x; q[d + 1] = t.y; q[d + 2] = t.z; q[d + 3] = t.w;
        }

        float sc[SETSZ];
        float mx = -1e30f;
#pragma unroll
        for (int m = 0; m < SETSZ; m++) {
            const float* kp = Ks + m * CDIM + h * 32;
            float a = 0.f;
#pragma unroll
            for (int d = 0; d < 32; d++) a += q[d] * kp[d];
            a *= 0.17677669529663687f;          // 1/sqrt(32)
            if (ms[m]) a = -1e30f;
            sc[m] = a;
            mx = fmaxf(mx, a);
        }
        float den = 0.f;
#pragma unroll
        for (int m = 0; m < SETSZ; m++) {
            float e = ms[m] ? 0.f : __expf(sc[m] - mx);
            sc[m] = e;
            den += e;
        }
        float inv = 1.0f / den;

        float o[32];
#pragma unroll
        for (int d = 0; d < 32; d++) o[d] = 0.f;
#pragma unroll
        for (int m = 0; m < SETSZ; m++) {
            float a = sc[m] * inv;
            const float* vp = Vs + m * CDIM + h * 32;
#pragma unroll
            for (int d = 0; d < 32; d++) o[d] += a * vp[d];
        }
        float* op = out + (base + l) * 256 + h * 32;
#pragma unroll
        for (int d = 0; d < 32; d += 4)
            *(float4*)(op + d) = make_float4(o[d], o[d + 1], o[d + 2], o[d + 3]);
    }
}

// ------------------------- scatter + residual + LN1 (warp per set-row) -------------------------
__global__ void __launch_bounds__(256) k_scatter_ln(
    const float* __restrict__ xin, const float* __restrict__ proj,
    const int* __restrict__ inds, const float* __restrict__ gam,
    const float* __restrict__ bet, float* __restrict__ out)
{
    int r = (blockIdx.x * 256 + threadIdx.x) >> 5;
    int lane = threadIdx.x & 31;
    int v = inds[r];
    const float4* x4 = (const float4*)(xin + (size_t)v * CDIM);
    const float4* p4 = (const float4*)(proj + (size_t)r * CDIM);
    float4 a0 = x4[lane],      b0 = p4[lane];
    float4 a1 = x4[lane + 32], b1 = p4[lane + 32];
    float4 y0 = make_float4(a0.x + b0.x, a0.y + b0.y, a0.z + b0.z, a0.w + b0.w);
    float4 y1 = make_float4(a1.x + b1.x, a1.y + b1.y, a1.z + b1.z, a1.w + b1.w);
    float s  = y0.x + y0.y + y0.z + y0.w + y1.x + y1.y + y1.z + y1.w;
    float s2 = y0.x*y0.x + y0.y*y0.y + y0.z*y0.z + y0.w*y0.w
             + y1.x*y1.x + y1.y*y1.y + y1.z*y1.z + y1.w*y1.w;
    s = warp_sum(s); s2 = warp_sum(s2);
    float mean = s * (1.0f / CDIM);
    float inv  = rsqrtf(s2 * (1.0f / CDIM) - mean * mean + 1e-5f);
    float4 g0 = ((const float4*)gam)[lane],      g1 = ((const float4*)gam)[lane + 32];
    float4 c0 = ((const float4*)bet)[lane],      c1 = ((const float4*)bet)[lane + 32];
    float4 o0 = make_float4((y0.x - mean) * inv * g0.x + c0.x, (y0.y - mean) * inv * g0.y + c0.y,
                            (y0.z - mean) * inv * g0.z + c0.z, (y0.w - mean) * inv * g0.w + c0.w);
    float4 o1 = make_float4((y1.x - mean) * inv * g1.x + c1.x, (y1.y - mean) * inv * g1.y + c1.y,
                            (y1.z - mean) * inv * g1.z + c1.z, (y1.w - mean) * inv * g1.w + c1.w);
    ((float4*)(out + (size_t)v * CDIM))[lane]      = o0;
    ((float4*)(out + (size_t)v * CDIM))[lane + 32] = o1;
}

// ------------------------- LN2 then LN3 fused (warp per voxel row) -------------------------
__global__ void __launch_bounds__(256) k_ln2_ln3(
    const float* x1, const float* __restrict__ ff,
    const float* __restrict__ idn,
    const float* __restrict__ g2, const float* __restrict__ b2,
    const float* __restrict__ g3, const float* __restrict__ b3,
    float* out)
{
    int r = (blockIdx.x * 256 + threadIdx.x) >> 5;
    int lane = threadIdx.x & 31;
    const float4* a4 = (const float4*)(x1 + (size_t)r * CDIM);
    const float4* f4 = (const float4*)(ff + (size_t)r * CDIM);
    float4 a0 = a4[lane],      c0 = f4[lane];
    float4 a1 = a4[lane + 32], c1 = f4[lane + 32];
    float4 y0 = make_float4(a0.x + c0.x, a0.y + c0.y, a0.z + c0.z, a0.w + c0.w);
    float4 y1 = make_float4(a1.x + c1.x, a1.y + c1.y, a1.z + c1.z, a1.w + c1.w);
    float s  = y0.x + y0.y + y0.z + y0.w + y1.x + y1.y + y1.z + y1.w;
    float s2 = y0.x*y0.x + y0.y*y0.y + y0.z*y0.z + y0.w*y0.w
             + y1.x*y1.x + y1.y*y1.y + y1.z*y1.z + y1.w*y1.w;
    s = warp_sum(s); s2 = warp_sum(s2);
    float mean = s * (1.0f / CDIM);
    float inv  = rsqrtf(s2 * (1.0f / CDIM) - mean * mean + 1e-5f);
    float4 g20 = ((const float4*)g2)[lane],      g21 = ((const float4*)g2)[lane + 32];
    float4 b20 = ((const float4*)b2)[lane],      b21 = ((const float4*)b2)[lane + 32];
    const float4* i4 = (const float4*)(idn + (size_t)r * CDIM);
    float4 i0 = i4[lane], i1 = i4[lane + 32];
    float4 z0 = make_float4((y0.x - mean) * inv * g20.x + b20.x + i0.x,
                            (y0.y - mean) * inv * g20.y + b20.y + i0.y,
                            (y0.z - mean) * inv * g20.z + b20.z + i0.z,
                            (y0.w - mean) * inv * g20.w + b20.w + i0.w);
    float4 z1 = make_float4((y1.x - mean) * inv * g21.x + b21.x + i1.x,
                            (y1.y - mean) * inv * g21.y + b21.y + i1.y,
                            (y1.z - mean) * inv * g21.z + b21.z + i1.z,
                            (y1.w - mean) * inv * g21.w + b21.w + i1.w);
    float t  = z0.x + z0.y + z0.z + z0.w + z1.x + z1.y + z1.z + z1.w;
    float t2 = z0.x*z0.x + z0.y*z0.y + z0.z*z0.z + z0.w*z0.w
             + z1.x*z1.x + z1.y*z1.y + z1.z*z1.z + z1.w*z1.w;
    t = warp_sum(t); t2 = warp_sum(t2);
    float mean2 = t * (1.0f / CDIM);
    float inv2  = rsqrtf(t2 * (1.0f / CDIM) - mean2 * mean2 + 1e-5f);
    float4 g30 = ((const float4*)g3)[lane],      g31 = ((const float4*)g3)[lane + 32];
    float4 b30 = ((const float4*)b3)[lane],      b31 = ((const float4*)b3)[lane + 32];
    float4 o0 = make_float4((z0.x - mean2) * inv2 * g30.x + b30.x, (z0.y - mean2) * inv2 * g30.y + b30.y,
                            (z0.z - mean2) * inv2 * g30.z + b30.z, (z0.w - mean2) * inv2 * g30.w + b30.w);
    float4 o1 = make_float4((z1.x - mean2) * inv2 * g31.x + b31.x, (z1.y - mean2) * inv2 * g31.y + b31.y,
                            (z1.z - mean2) * inv2 * g31.z + b31.z, (z1.w - mean2) * inv2 * g31.w + b31.w);
    ((float4*)(out + (size_t)r * CDIM))[lane]      = o0;
    ((float4*)(out + (size_t)r * CDIM))[lane + 32] = o1;
}

// ------------------------- block-end: LN(a + b) -------------------------
__global__ void __launch_bounds__(256) k_add_ln(
    const float* __restrict__ a, const float* b,
    const float* __restrict__ g, const float* __restrict__ be,
    float* out)
{
    int r = (blockIdx.x * 256 + threadIdx.x) >> 5;
    int lane = threadIdx.x & 31;
    const float4* a4 = (const float4*)(a + (size_t)r * CDIM);
    const float4* b4 = (const float4*)(b + (size_t)r * CDIM);
    float4 x0 = a4[lane],      x1 = a4[lane + 32];
    float4 c0 = b4[lane],      c1 = b4[lane + 32];
    float4 y0 = make_float4(x0.x + c0.x, x0.y + c0.y, x0.z + c0.z, x0.w + c0.w);
    float4 y1 = make_float4(x1.x + c1.x, x1.y + c1.y, x1.z + c1.z, x1.w + c1.w);
    float s  = y0.x + y0.y + y0.z + y0.w + y1.x + y1.y + y1.z + y1.w;
    float s2 = y0.x*y0.x + y0.y*y0.y + y0.z*y0.z + y0.w*y0.w
             + y1.x*y1.x + y1.y*y1.y + y1.z*y1.z + y1.w*y1.w;
    s = warp_sum(s); s2 = warp_sum(s2);
    float mean = s * (1.0f / CDIM);
    float inv  = rsqrtf(s2 * (1.0f / CDIM) - mean * mean + 1e-5f);
    float4 g0 = ((const float4*)g)[lane],  g1 = ((const float4*)g)[lane + 32];
    float4 e0 = ((const float4*)be)[lane], e1 = ((const float4*)be)[lane + 32];
    float4 o0 = make_float4((y0.x - mean) * inv * g0.x + e0.x, (y0.y - mean) * inv * g0.y + e0.y,
                            (y0.z - mean) * inv * g0.z + e0.z, (y0.w - mean) * inv * g0.w + e0.w);
    float4 o1 = make_float4((y1.x - mean) * inv * g1.x + e1.x, (y1.y - mean) * inv * g1.y + e1.y,
                            (y1.z - mean) * inv * g1.z + e1.z, (y1.w - mean) * inv * g1.w + e1.w);
    ((float4*)(out + (size_t)r * CDIM))[lane]      = o0;
    ((float4*)(out + (size_t)r * CDIM))[lane + 32] = o1;
}

// ------------------------- host -------------------------
static void launch_gemm(const float* A, const float* W, const float* bias,
                        float* C, int M, int Nn, int K, int act)
{
    dim3 grid(Nn / GBN, (M + GBM - 1) / GBM);
    k_mma_gemm<<<grid, 256, GEMM_SMEM>>>(A, W, bias, C, M, Nn, K, act);
}

extern "C" void kernel_launch(void* const* d_in, const int* in_sizes, int n_in,
                              void* d_out, int out_size)
{
    const float* src  = (const float*)d_in[0];
    const float* pos  = (const float*)d_in[1];
    const int*   inds = (const int*)d_in[2];
    const unsigned char* masks = (const unsigned char*)d_in[3];
    const float* ipw = (const float*)d_in[4];
    const float* ipb = (const float*)d_in[5];
    const float* ow  = (const float*)d_in[6];
    const float* ob  = (const float*)d_in[7];
    const float* l1w = (const float*)d_in[8];
    const float* l1b = (const float*)d_in[9];
    const float* l2w = (const float*)d_in[10];
    const float* l2b = (const float*)d_in[11];
    const float* n1g = (const float*)d_in[12];
    const float* n1b = (const float*)d_in[13];
    const float* n2g = (const float*)d_in[14];
    const float* n2b = (const float*)d_in[15];
    const float* eg  = (const float*)d_in[16];
    const float* eb  = (const float*)d_in[17];
    const float* rg  = (const float*)d_in[18];
    const float* rb  = (const float*)d_in[19];
    float* outp = (float*)d_out;

    void* pp; void* pmk;
    cudaGetSymbolAddress(&pp, g_pool);
    cudaGetSymbolAddress(&pmk, g_maskc);
    float* pool = (float*)pp;
    unsigned char* maskc = (unsigned char*)pmk;

    float* qko   = pool;            // 2NC
    float* vproj = pool + 2 * NC;   // 1NC
    float* att   = pool + 3 * NC;   // 1NC
    float* qk    = pool + 4 * NC;   // 1NC (-> proj -> ffo)
    float* proj  = qk;
    float* ffo   = qk;
    float* ffh   = pool;            // 4NC, aliases qko+vproj+att (dead by FF time)
    float* bufA  = pool + 5 * NC;
    float* bufB  = pool + 6 * NC;

    const int attn_smem = 2 * SETSZ * CDIM * (int)sizeof(float);  // 73728 B
    cudaFuncSetAttribute(k_attn, cudaFuncAttributeMaxDynamicSharedMemorySize, attn_smem);
    cudaFuncSetAttribute(k_mma_gemm, cudaFuncAttributeMaxDynamicSharedMemorySize, GEMM_SMEM);

    k_mask_detect<<<1, 256>>>(masks);
    k_mask_convert<<<(MTOT + 255) / 256, 256>>>(masks);

    const int gather_blocks = NTOT * 64 / 256;   // 65538
    const int ln_blocks     = NTOT / 8;          // 32769

    const float* cur = src;
    int lid = 0;
    for (int blk = 0; blk < 2; blk++) {
        const float* blockin = cur;
        for (int part = 0; part < 2; part++) {
            const int* ind = inds + (size_t)(blk * 2 + part) * NSETS * SETSZ;
            const unsigned char* msk = maskc + (size_t)(blk * 2 + part) * NSETS * SETSZ;
            const float* posl = pos + (size_t)(blk * 2 + part) * NC;

            k_gather_qk<<<gather_blocks, 256>>>(cur, posl, ind, qk);
            launch_gemm(qk, ipw + (size_t)lid * 3 * CDIM * CDIM,
                        ipb + (size_t)lid * 3 * CDIM, qko, NTOT, 2 * CDIM, CDIM, 0);
            launch_gemm(cur, ipw + (size_t)lid * 3 * CDIM * CDIM + 2 * CDIM * CDIM,
                        ipb + (size_t)lid * 3 * CDIM + 2 * CDIM, vproj, NTOT, CDIM, CDIM, 0);
            k_attn<<<NSETS, 256, attn_smem>>>(qko, vproj, ind, msk, att);
            launch_gemm(att, ow + (size_t)lid * CDIM * CDIM,
                        ob + (size_t)lid * CDIM, proj, NTOT, CDIM, CDIM, 0);
            float* lout = (part == 0) ? bufA : bufB;
            float* x1 = lout;
            k_scatter_ln<<<ln_blocks, 256>>>(cur, proj, ind,
                                             n1g + (size_t)lid * CDIM, n1b + (size_t)lid * CDIM, x1);
            launch_gemm(x1, l1w + (size_t)lid * DFFN * CDIM,
                        l1b + (size_t)lid * DFFN, ffh, NTOT, DFFN, CDIM, 1);
            launch_gemm(ffh, l2w + (size_t)lid * CDIM * DFFN,
                        l2b + (size_t)lid * CDIM, ffo, NTOT, CDIM, DFFN, 0);
            k_ln2_ln3<<<ln_blocks, 256>>>(x1, ffo, cur,
                                          n2g + (size_t)lid * CDIM, n2b + (size_t)lid * CDIM,
                                          eg + (size_t)lid * CDIM,  eb + (size_t)lid * CDIM, lout);
            cur = lout;
            lid++;
        }
        k_add_ln<<<ln_blocks, 256>>>(cur, blockin,
                                     rg + (size_t)blk * CDIM, rb + (size_t)blk * CDIM, outp);
        cur = outp;
    }
}

// round 16
// speedup vs baseline: 1.9370x; 1.0029x over previous
#include <cuda_runtime.h>
#include <cuda_bf16.h>

#define NTOT 262152
#define CDIM 256
#define DFFN 1024
#define NSETS 7282
#define SETSZ 36
#define MTOT (2*2*NSETS*SETSZ)   // 1048608
#define NC   ((size_t)NTOT * CDIM)
#define NCH  (NC / 2)            // floats occupied by one bf16 plane of NC elements

// ------------------------- scratch (device globals; no allocation) -------------------------
// Pool 9*NC + 3.15M floats = 2.43 GB (inside aarch64 ±4GB reloc window).
// Region liveness (per layer steps 1..9):
//  [0,4NC)   : qk planes [0,NC) | qko fp32 [NC,3NC) | att planes [3NC,4NC)   (steps 1-5)
//              then ffh planes (4NC bf16-equiv) for FF1->FF2                  (steps 7-8)
//  [4NC,5NC) : vproj fp32 (3-4) then proj fp32 (5-6)
//  [5NC,6NC) : x1 planes (6-7) then ffo fp32 (8-9)
//  [6NC,7NC) : cur planes (written by prev layer LN / src split; read step 3)
//  [7NC,8NC) : bufA     [8NC,9NC) : bufB
//  [9NC,..)  : weight planes (3,145,728 floats)
__device__ float g_pool[9 * NC + 3145728];
__device__ unsigned char g_maskc[MTOT];
__device__ int g_mask_flag;

__device__ __forceinline__ float warp_sum(float v) {
#pragma unroll
    for (int o = 16; o; o >>= 1) v += __shfl_xor_sync(0xffffffffu, v, o);
    return v;
}

// split float4 -> 4 hi bf16 + 4 lo bf16, one 8B store per plane
__device__ __forceinline__ void plane_store4(__nv_bfloat16* hi, __nv_bfloat16* lo,
                                             size_t idx, float4 v) {
    __nv_bfloat162 h0 = __float22bfloat162_rn(make_float2(v.x, v.y));
    __nv_bfloat162 h1 = __float22bfloat162_rn(make_float2(v.z, v.w));
    float2 f0 = __bfloat1622float2(h0), f1 = __bfloat1622float2(h1);
    __nv_bfloat162 l0 = __float22bfloat162_rn(make_float2(v.x - f0.x, v.y - f0.y));
    __nv_bfloat162 l1 = __float22bfloat162_rn(make_float2(v.z - f1.x, v.w - f1.y));
    uint2 hu, lu;
    hu.x = *(unsigned*)&h0; hu.y = *(unsigned*)&h1;
    lu.x = *(unsigned*)&l0; lu.y = *(unsigned*)&l1;
    *(uint2*)(hi + idx) = hu;
    *(uint2*)(lo + idx) = lu;
}

// ------------------------- generic fp32 -> bf16 hi/lo split -------------------------
__global__ void __launch_bounds__(256) k_split(
    const float* __restrict__ src, __nv_bfloat16* __restrict__ hi,
    __nv_bfloat16* __restrict__ lo, int n4)
{
    int i = blockIdx.x * 256 + threadIdx.x;
    if (i >= n4) return;
    float4 v = ((const float4*)src)[i];
    plane_store4(hi, lo, (size_t)i * 4, v);
}

// ------------------------- mask dtype detection + canonicalization -------------------------
__global__ void k_mask_detect(const unsigned char* __restrict__ raw) {
    __shared__ unsigned int slo[256], shi[256];
    unsigned int lo = 0, hi = 0;
    for (int i = threadIdx.x; i < 65536; i += 256) {
        unsigned int b = raw[i];
        if ((i & 3) == 0) lo |= b; else hi |= b;
    }
    slo[threadIdx.x] = lo; shi[threadIdx.x] = hi;
    __syncthreads();
    if (threadIdx.x == 0) {
        for (int i = 1; i < 256; i++) { lo |= slo[i]; hi |= shi[i]; }
        int flag;
        if (hi == 0)       flag = 1;   // int32
        else if (lo != 0)  flag = 0;   // uint8
        else               flag = 2;   // float32
        g_mask_flag = flag;
    }
}

__global__ void k_mask_convert(const unsigned char* __restrict__ raw) {
    int i = blockIdx.x * 256 + threadIdx.x;
    if (i >= MTOT) return;
    int f = g_mask_flag;
    unsigned char v;
    if (f == 0)      v = (raw[i] != 0);
    else if (f == 1) v = (((const int*)raw)[i] != 0);
    else             v = (((const float*)raw)[i] != 0.0f);
    g_maskc[i] = v;
}

// ------------------------- gather: qk = x[ind] + pos[ind] -> bf16 planes (set order) ----
__global__ void __launch_bounds__(256) k_gather_qk(
    const float* __restrict__ x, const float* __restrict__ pos,
    const int* __restrict__ inds,
    __nv_bfloat16* __restrict__ qh, __nv_bfloat16* __restrict__ ql)
{
    int idx = blockIdx.x * 256 + threadIdx.x;   // NTOT*64 threads exactly
    int r = idx >> 6;
    int c = idx & 63;
    int v = inds[r];
    float4 xv = ((const float4*)x)[(size_t)v * 64 + c];
    float4 pv = ((const float4*)pos)[(size_t)v * 64 + c];
    float4 s = make_float4(xv.x + pv.x, xv.y + pv.y, xv.z + pv.z, xv.w + pv.w);
    plane_store4(qh, ql, (size_t)r * 256 + (size_t)c * 4, s);
}

// ============================================================================
// bf16x3 plane GEMM v3: C = A @ W^T + bias; A,W given as bf16 hi/lo planes.
// acc = Ah*Wh + Ah*Wl + Al*Wh (fp32 accumulate). Zero conversions in kernel.
// CTA tile 256x128x32, 8 warps 4(m)x2(n), 3-stage cp.async pipeline.
// SMEM row stride 20 words (32 bf16 + 8 pad) -> conflict-free frags.
// mode 0: fp32 out. mode 1: exact-GELU + bf16 hi/lo plane out.
// ============================================================================
#define GBM 256
#define GBN 128
#define GBK 32
#define ROWW 20
#define OFF_AH 0
#define OFF_AL (GBM * ROWW)             // 5120
#define OFF_BH (2 * GBM * ROWW)         // 10240
#define OFF_BL (OFF_BH + GBN * ROWW)    // 12800
#define STAGE_WORDS (OFF_BL + GBN * ROWW)   // 15360
#define NSTAGE 3
#define GEMM_SMEM (NSTAGE * STAGE_WORDS * 4)  // 184320 bytes

__device__ __forceinline__ void mma16816(float* c, const unsigned* a, const unsigned* b) {
    asm volatile(
        "mma.sync.aligned.m16n8k16.row.col.f32.bf16.bf16.f32 "
        "{%0,%1,%2,%3}, {%4,%5,%6,%7}, {%8,%9}, {%0,%1,%2,%3};\n"
        : "+f"(c[0]), "+f"(c[1]), "+f"(c[2]), "+f"(c[3])
        : "r"(a[0]), "r"(a[1]), "r"(a[2]), "r"(a[3]), "r"(b[0]), "r"(b[1]));
}

__device__ __forceinline__ float gelu_exact(float x) {
    return 0.5f * x * (1.0f + erff(x * 0.70710678118654752f));
}

__global__ void __launch_bounds__(256, 1) k_mma_gemm(
    const __nv_bfloat16* __restrict__ Ah, const __nv_bfloat16* __restrict__ Al,
    const __nv_bfloat16* __restrict__ Wh, const __nv_bfloat16* __restrict__ Wl,
    const float* __restrict__ bias, float* __restrict__ Cf,
    __nv_bfloat16* __restrict__ Chi, __nv_bfloat16* __restrict__ Clo,
    int M, int Nn, int K, int mode)
{
    extern __shared__ __align__(16) unsigned usm[];
    int tid  = threadIdx.x;
    int lane = tid & 31;
    int wid  = tid >> 5;
    int wm   = wid >> 1;    // 0..3
    int wn   = wid & 1;     // 0..1
    int row0 = blockIdx.y * GBM;
    int col0 = blockIdx.x * GBN;
    int g    = lane >> 2;
    int l3   = lane & 3;

    unsigned sbase = (unsigned)__cvta_generic_to_shared(usm);

    float acc[4][8][4];
#pragma unroll
    for (int mt = 0; mt < 4; mt++)
#pragma unroll
        for (int nt = 0; nt < 8; nt++)
#pragma unroll
            for (int e = 0; e < 4; e++) acc[mt][nt][e] = 0.f;

    int rr = tid >> 2;       // 0..63
    int cc = tid & 3;        // 16B chunk within 64B row

    auto load_stage = [&](int st, int k0) {
        unsigned s0 = sbase + (unsigned)(st * STAGE_WORDS) * 4u;
        const __nv_bfloat16* pAh = Ah + (size_t)(row0 + rr) * K + k0 + cc * 8;
        const __nv_bfloat16* pAl = Al + (size_t)(row0 + rr) * K + k0 + cc * 8;
        unsigned da = s0 + (unsigned)(rr * ROWW + cc * 4) * 4u;
#pragma unroll
        for (int p = 0; p < 4; p++) {
            int grow = row0 + p * 64 + rr;
            int sz = (grow < M) ? 16 : 0;
            unsigned off = (unsigned)(p * 64 * ROWW) * 4u;
            asm volatile("cp.async.cg.shared.global [%0], [%1], 16, %2;\n"
                :: "r"(da + off), "l"(pAh + (size_t)p * 64 * K), "r"(sz));
            asm volatile("cp.async.cg.shared.global [%0], [%1], 16, %2;\n"
                :: "r"(da + (unsigned)OFF_AL * 4u + off), "l"(pAl + (size_t)p * 64 * K), "r"(sz));
        }
        const __nv_bfloat16* pWh = Wh + (size_t)(col0 + rr) * K + k0 + cc * 8;
        const __nv_bfloat16* pWl = Wl + (size_t)(col0 + rr) * K + k0 + cc * 8;
        unsigned db = s0 + (unsigned)(OFF_BH + rr * ROWW + cc * 4) * 4u;
#pragma unroll
        for (int p = 0; p < 2; p++) {
            unsigned off = (unsigned)(p * 64 * ROWW) * 4u;
            asm volatile("cp.async.cg.shared.global [%0], [%1], 16;\n"
                :: "r"(db + off), "l"(pWh + (size_t)p * 64 * K));
            asm volatile("cp.async.cg.shared.global [%0], [%1], 16;\n"
                :: "r"(db + (unsigned)(OFF_BL - OFF_BH) * 4u + off), "l"(pWl + (size_t)p * 64 * K));
        }
        asm volatile("cp.async.commit_group;\n");
    };

    auto compute_stage = [&](int st) {
        const unsigned* S = usm + (size_t)st * STAGE_WORDS;
#pragma unroll
        for (int h = 0; h < 2; h++) {
            int kw = h * 8 + l3;
            unsigned ah[4][4], al[4][4];
#pragma unroll
            for (int mt = 0; mt < 4; mt++) {
                int r0w = (wm * 64 + mt * 16 + g) * ROWW + kw;
                int r1w = r0w + 8 * ROWW;
                ah[mt][0] = S[OFF_AH + r0w];
                ah[mt][1] = S[OFF_AH + r1w];
                ah[mt][2] = S[OFF_AH + r0w + 4];
                ah[mt][3] = S[OFF_AH + r1w + 4];
                al[mt][0] = S[OFF_AL + r0w];
                al[mt][1] = S[OFF_AL + r1w];
                al[mt][2] = S[OFF_AL + r0w + 4];
                al[mt][3] = S[OFF_AL + r1w + 4];
            }
#pragma unroll
            for (int nt = 0; nt < 8; nt++) {
                int nw = (wn * 64 + nt * 8 + g) * ROWW + kw;
                unsigned bh[2] = { S[OFF_BH + nw], S[OFF_BH + nw + 4] };
                unsigned bl[2] = { S[OFF_BL + nw], S[OFF_BL + nw + 4] };
#pragma unroll
                for (int mt = 0; mt < 4; mt++) {
                    float* c = acc[mt][nt];
                    mma16816(c, ah[mt], bh);   // hi*hi
                    mma16816(c, ah[mt], bl);   // hi*lo
                    mma16816(c, al[mt], bh);   // lo*hi
                }
            }
        }
    };

    int T = K / GBK;
    load_stage(0, 0);
    if (T > 1) load_stage(1, GBK);
    for (int t = 0; t < T; t++) {
        if (t + 2 <= T) asm volatile("cp.async.wait_group 1;\n");
        else            asm volatile("cp.async.wait_group 0;\n");
        __syncthreads();
        if (t + 2 < T) load_stage((t + 2) % NSTAGE, (t + 2) * GBK);
        compute_stage(t % NSTAGE);
    }

    // epilogue
#pragma unroll
    for (int mt = 0; mt < 4; mt++) {
        int rlo = row0 + wm * 64 + mt * 16 + g;
        int rhi = rlo + 8;
#pragma unroll
        for (int nt = 0; nt < 8; nt++) {
            int cn = col0 + wn * 64 + nt * 8 + 2 * l3;
            float2 bb = *(const float2*)(bias + cn);
            float* c = acc[mt][nt];
            float x0 = c[0] + bb.x, x1 = c[1] + bb.y;
            float x2 = c[2] + bb.x, x3 = c[3] + bb.y;
            if (mode == 0) {
                if (rlo < M) *(float2*)(Cf + (size_t)rlo * Nn + cn) = make_float2(x0, x1);
                if (rhi < M) *(float2*)(Cf + (size_t)rhi * Nn + cn) = make_float2(x2, x3);
            } else {
                if (rlo < M) {
                    float2 v = make_float2(gelu_exact(x0), gelu_exact(x1));
                    __nv_bfloat162 h2 = __float22bfloat162_rn(v);
                    float2 f = __bfloat1622float2(h2);
                    __nv_bfloat162 l2 = __float22bfloat162_rn(make_float2(v.x - f.x, v.y - f.y));
                    *(unsigned*)(Chi + (size_t)rlo * Nn + cn) = *(unsigned*)&h2;
                    *(unsigned*)(Clo + (size_t)rlo * Nn + cn) = *(unsigned*)&l2;
                }
                if (rhi < M) {
                    float2 v = make_float2(gelu_exact(x2), gelu_exact(x3));
                    __nv_bfloat162 h2 = __float22bfloat162_rn(v);
                    float2 f = __bfloat1622float2(h2);
                    __nv_bfloat162 l2 = __float22bfloat162_rn(make_float2(v.x - f.x, v.y - f.y));
                    *(unsigned*)(Chi + (size_t)rhi * Nn + cn) = *(unsigned*)&h2;
                    *(unsigned*)(Clo + (size_t)rhi * Nn + cn) = *(unsigned*)&l2;
                }
            }
        }
    }
}

// ------------------------- per-set masked MHA (bf16 plane output) -------------------------
__global__ void __launch_bounds__(256) k_attn(
    const float* __restrict__ qko,    // N x 512 : [0:256)=Q, [256:512)=K (set order)
    const float* __restrict__ vproj,  // N x 256 (voxel order)
    const int* __restrict__ inds,
    const unsigned char* __restrict__ mask,
    __nv_bfloat16* __restrict__ oh, __nv_bfloat16* __restrict__ ol)
{
    extern __shared__ float sm[];
    float* Ks = sm;
    float* Vs = sm + SETSZ * CDIM;
    __shared__ unsigned char ms[SETSZ];
    __shared__ int vind[SETSZ];

    int s   = blockIdx.x;
    int tid = threadIdx.x;
    size_t base = (size_t)s * SETSZ;

    if (tid < SETSZ) { ms[tid] = mask[base + tid]; vind[tid] = inds[base + tid]; }
    __syncthreads();

    for (int i = tid; i < SETSZ * 64; i += 256) {
        int m = i >> 6, c = i & 63;
        ((float4*)Ks)[(size_t)m * 64 + c] = *((const float4*)(qko + (base + m) * 512 + 256) + c);
        ((float4*)Vs)[(size_t)m * 64 + c] = ((const float4*)vproj)[(size_t)vind[m] * 64 + c];
    }
    __syncthreads();

    for (int pair = tid; pair < SETSZ * 8; pair += 256) {
        int h = pair / SETSZ;
        int l = pair % SETSZ;

        const float* qp = qko + (base + l) * 512 + h * 32;
        float q[32];
#pragma unroll
        for (int d = 0; d < 32; d += 4) {
            float4 t = *(const float4*)(qp + d);
            q[d] = t.x; q[d + 1] = t.y; q[d + 2] = t.z; q[d + 3] = t.w;
        }

        float sc[SETSZ];
        float mx = -1e30f;
#pragma unroll
        for (int m = 0; m < SETSZ; m++) {
            const float* kp = Ks + m * CDIM + h * 32;
            float a = 0.f;
#pragma unroll
            for (int d = 0; d < 32; d++) a += q[d] * kp[d];
            a *= 0.17677669529663687f;
            if (ms[m]) a = -1e30f;
            sc[m] = a;
            mx = fmaxf(mx, a);
        }
        float den = 0.f;
#pragma unroll
        for (int m = 0; m < SETSZ; m++) {
            float e = ms[m] ? 0.f : __expf(sc[m] - mx);
            sc[m] = e;
            den += e;
        }
        float inv = 1.0f / den;

        float o[32];
#pragma unroll
        for (int d = 0; d < 32; d++) o[d] = 0.f;
#pragma unroll
        for (int m = 0; m < SETSZ; m++) {
            float a = sc[m] * inv;
            const float* vp = Vs + m * CDIM + h * 32;
#pragma unroll
            for (int d = 0; d < 32; d++) o[d] += a * vp[d];
        }
        size_t ob = (base + l) * 256 + h * 32;
#pragma unroll
        for (int d = 0; d < 32; d += 4)
            plane_store4(oh, ol, ob + d, make_float4(o[d], o[d + 1], o[d + 2], o[d + 3]));
    }
}

// ------------------------- scatter + residual + LN1 (+ x1 planes) -------------------------
__global__ void __launch_bounds__(256) k_scatter_ln(
    const float* __restrict__ xin, const float* __restrict__ proj,
    const int* __restrict__ inds, const float* __restrict__ gam,
    const float* __restrict__ bet, float* __restrict__ out,
    __nv_bfloat16* __restrict__ x1h, __nv_bfloat16* __restrict__ x1l)
{
    int r = (blockIdx.x * 256 + threadIdx.x) >> 5;
    int lane = threadIdx.x & 31;
    int v = inds[r];
    const float4* x4 = (const float4*)(xin + (size_t)v * CDIM);
    const float4* p4 = (const float4*)(proj + (size_t)r * CDIM);
    float4 a0 = x4[lane],      b0 = p4[lane];
    float4 a1 = x4[lane + 32], b1 = p4[lane + 32];
    float4 y0 = make_float4(a0.x + b0.x, a0.y + b0.y, a0.z + b0.z, a0.w + b0.w);
    float4 y1 = make_float4(a1.x + b1.x, a1.y + b1.y, a1.z + b1.z, a1.w + b1.w);
    float s  = y0.x + y0.y + y0.z + y0.w + y1.x + y1.y + y1.z + y1.w;
    float s2 = y0.x*y0.x + y0.y*y0.y + y0.z*y0.z + y0.w*y0.w
             + y1.x*y1.x + y1.y*y1.y + y1.z*y1.z + y1.w*y1.w;
    s = warp_sum(s); s2 = warp_sum(s2);
    float mean = s * (1.0f / CDIM);
    float inv  = rsqrtf(s2 * (1.0f / CDIM) - mean * mean + 1e-5f);
    float4 g0 = ((const float4*)gam)[lane],      g1 = ((const float4*)gam)[lane + 32];
    float4 c0 = ((const float4*)bet)[lane],      c1 = ((const float4*)bet)[lane + 32];
    float4 o0 = make_float4((y0.x - mean) * inv * g0.x + c0.x, (y0.y - mean) * inv * g0.y + c0.y,
                            (y0.z - mean) * inv * g0.z + c0.z, (y0.w - mean) * inv * g0.w + c0.w);
    float4 o1 = make_float4((y1.x - mean) * inv * g1.x + c1.x, (y1.y - mean) * inv * g1.y + c1.y,
                            (y1.z - mean) * inv * g1.z + c1.z, (y1.w - mean) * inv * g1.w + c1.w);
    ((float4*)(out + (size_t)v * CDIM))[lane]      = o0;
    ((float4*)(out + (size_t)v * CDIM))[lane + 32] = o1;
    size_t e = (size_t)v * CDIM + lane * 4;
    plane_store4(x1h, x1l, e, o0);
    plane_store4(x1h, x1l, e + 128, o1);
}

// ------------------------- LN2 then LN3 fused (+ optional cur planes) ----------------------
__global__ void __launch_bounds__(256) k_ln2_ln3(
    const float* x1, const float* __restrict__ ff,
    const float* __restrict__ idn,
    const float* __restrict__ g2, const float* __restrict__ b2,
    const float* __restrict__ g3, const float* __restrict__ b3,
    float* out, __nv_bfloat16* __restrict__ ch, __nv_bfloat16* __restrict__ cl, int emit)
{
    int r = (blockIdx.x * 256 + threadIdx.x) >> 5;
    int lane = threadIdx.x & 31;
    const float4* a4 = (const float4*)(x1 + (size_t)r * CDIM);
    const float4* f4 = (const float4*)(ff + (size_t)r * CDIM);
    float4 a0 = a4[lane],      c0 = f4[lane];
    float4 a1 = a4[lane + 32], c1 = f4[lane + 32];
    float4 y0 = make_float4(a0.x + c0.x, a0.y + c0.y, a0.z + c0.z, a0.w + c0.w);
    float4 y1 = make_float4(a1.x + c1.x, a1.y + c1.y, a1.z + c1.z, a1.w + c1.w);
    float s  = y0.x + y0.y + y0.z + y0.w + y1.x + y1.y + y1.z + y1.w;
    float s2 = y0.x*y0.x + y0.y*y0.y + y0.z*y0.z + y0.w*y0.w
             + y1.x*y1.x + y1.y*y1.y + y1.z*y1.z + y1.w*y1.w;
    s = warp_sum(s); s2 = warp_sum(s2);
    float mean = s * (1.0f / CDIM);
    float inv  = rsqrtf(s2 * (1.0f / CDIM) - mean * mean + 1e-5f);
    float4 g20 = ((const float4*)g2)[lane],      g21 = ((const float4*)g2)[lane + 32];
    float4 b20 = ((const float4*)b2)[lane],      b21 = ((const float4*)b2)[lane + 32];
    const float4* i4 = (const float4*)(idn + (size_t)r * CDIM);
    float4 i0 = i4[lane], i1 = i4[lane + 32];
    float4 z0 = make_float4((y0.x - mean) * inv * g20.x + b20.x + i0.x,
                            (y0.y - mean) * inv * g20.y + b20.y + i0.y,
                            (y0.z - mean) * inv * g20.z + b20.z + i0.z,
                            (y0.w - mean) * inv * g20.w + b20.w + i0.w);
    float4 z1 = make_float4((y1.x - mean) * inv * g21.x + b21.x + i1.x,
                            (y1.y - mean) * inv * g21.y + b21.y + i1.y,
                            (y1.z - mean) * inv * g21.z + b21.z + i1.z,
                            (y1.w - mean) * inv * g21.w + b21.w + i1.w);
    float t  = z0.x + z0.y + z0.z + z0.w + z1.x + z1.y + z1.z + z1.w;
    float t2 = z0.x*z0.x + z0.y*z0.y + z0.z*z0.z + z0.w*z0.w
             + z1.x*z1.x + z1.y*z1.y + z1.z*z1.z + z1.w*z1.w;
    t = warp_sum(t); t2 = warp_sum(t2);
    float mean2 = t * (1.0f / CDIM);
    float inv2  = rsqrtf(t2 * (1.0f / CDIM) - mean2 * mean2 + 1e-5f);
    float4 g30 = ((const float4*)g3)[lane],      g31 = ((const float4*)g3)[lane + 32];
    float4 b30 = ((const float4*)b3)[lane],      b31 = ((const float4*)b3)[lane + 32];
    float4 o0 = make_float4((z0.x - mean2) * inv2 * g30.x + b30.x, (z0.y - mean2) * inv2 * g30.y + b30.y,
                            (z0.z - mean2) * inv2 * g30.z + b30.z, (z0.w - mean2) * inv2 * g30.w + b30.w);
    float4 o1 = make_float4((z1.x - mean2) * inv2 * g31.x + b31.x, (z1.y - mean2) * inv2 * g31.y + b31.y,
                            (z1.z - mean2) * inv2 * g31.z + b31.z, (z1.w - mean2) * inv2 * g31.w + b31.w);
    ((float4*)(out + (size_t)r * CDIM))[lane]      = o0;
    ((float4*)(out + (size_t)r * CDIM))[lane + 32] = o1;
    if (emit) {
        size_t e = (size_t)r * CDIM + lane * 4;
        plane_store4(ch, cl, e, o0);
        plane_store4(ch, cl, e + 128, o1);
    }
}

// ------------------------- block-end: LN(a + b) (+ optional cur planes) -------------------
__global__ void __launch_bounds__(256) k_add_ln(
    const float* __restrict__ a, const float* b,
    const float* __restrict__ g, const float* __restrict__ be,
    float* out, __nv_bfloat16* __restrict__ ch, __nv_bfloat16* __restrict__ cl, int emit)
{
    int r = (blockIdx.x * 256 + threadIdx.x) >> 5;
    int lane = threadIdx.x & 31;
    const float4* a4 = (const float4*)(a + (size_t)r * CDIM);
    const float4* b4 = (const float4*)(b + (size_t)r * CDIM);
    float4 x0 = a4[lane],      x1 = a4[lane + 32];
    float4 c0 = b4[lane],      c1 = b4[lane + 32];
    float4 y0 = make_float4(x0.x + c0.x, x0.y + c0.y, x0.z + c0.z, x0.w + c0.w);
    float4 y1 = make_float4(x1.x + c1.x, x1.y + c1.y, x1.z + c1.z, x1.w + c1.w);
    float s  = y0.x + y0.y + y0.z + y0.w + y1.x + y1.y + y1.z + y1.w;
    float s2 = y0.x*y0.x + y0.y*y0.y + y0.z*y0.z + y0.w*y0.w
             + y1.x*y1.x + y1.y*y1.y + y1.z*y1.z + y1.w*y1.w;
    s = warp_sum(s); s2 = warp_sum(s2);
    float mean = s * (1.0f / CDIM);
    float inv  = rsqrtf(s2 * (1.0f / CDIM) - mean * mean + 1e-5f);
    float4 g0 = ((const float4*)g)[lane],  g1 = ((const float4*)g)[lane + 32];
    float4 e0 = ((const float4*)be)[lane], e1 = ((const float4*)be)[lane + 32];
    float4 o0 = make_float4((y0.x - mean) * inv * g0.x + e0.x, (y0.y - mean) * inv * g0.y + e0.y,
                            (y0.z - mean) * inv * g0.z + e0.z, (y0.w - mean) * inv * g0.w + e0.w);
    float4 o1 = make_float4((y1.x - mean) * inv * g1.x + e1.x, (y1.y - mean) * inv * g1.y + e1.y,
                            (y1.z - mean) * inv * g1.z + e1.z, (y1.w - mean) * inv * g1.w + e1.w);
    ((float4*)(out + (size_t)r * CDIM))[lane]      = o0;
    ((float4*)(out + (size_t)r * CDIM))[lane + 32] = o1;
    if (emit) {
        size_t e = (size_t)r * CDIM + lane * 4;
        plane_store4(ch, cl, e, o0);
        plane_store4(ch, cl, e + 128, o1);
    }
}

// ------------------------- host -------------------------
static void launch_gemm(const __nv_bfloat16* Ah, const __nv_bfloat16* Al,
                        const __nv_bfloat16* Wh, const __nv_bfloat16* Wl,
                        const float* bias, float* Cf,
                        __nv_bfloat16* Chi, __nv_bfloat16* Clo,
                        int M, int Nn, int K, int mode)
{
    dim3 grid(Nn / GBN, (M + GBM - 1) / GBM);
    k_mma_gemm<<<grid, 256, GEMM_SMEM>>>(Ah, Al, Wh, Wl, bias, Cf, Chi, Clo, M, Nn, K, mode);
}

extern "C" void kernel_launch(void* const* d_in, const int* in_sizes, int n_in,
                              void* d_out, int out_size)
{
    const float* src  = (const float*)d_in[0];
    const float* pos  = (const float*)d_in[1];
    const int*   inds = (const int*)d_in[2];
    const unsigned char* masks = (const unsigned char*)d_in[3];
    const float* ipw = (const float*)d_in[4];
    const float* ipb = (const float*)d_in[5];
    const float* ow  = (const float*)d_in[6];
    const float* ob  = (const float*)d_in[7];
    const float* l1w = (const float*)d_in[8];
    const float* l1b = (const float*)d_in[9];
    const float* l2w = (const float*)d_in[10];
    const float* l2b = (const float*)d_in[11];
    const float* n1g = (const float*)d_in[12];
    const float* n1b = (const float*)d_in[13];
    const float* n2g = (const float*)d_in[14];
    const float* n2b = (const float*)d_in[15];
    const float* eg  = (const float*)d_in[16];
    const float* eb  = (const float*)d_in[17];
    const float* rg  = (const float*)d_in[18];
    const float* rb  = (const float*)d_in[19];
    float* outp = (float*)d_out;

    void* pp; void* pmk;
    cudaGetSymbolAddress(&pp, g_pool);
    cudaGetSymbolAddress(&pmk, g_maskc);
    float* pool = (float*)pp;
    unsigned char* maskc = (unsigned char*)pmk;

    __nv_bfloat16* qk_hi  = (__nv_bfloat16*)pool;
    __nv_bfloat16* qk_lo  = (__nv_bfloat16*)(pool + NCH);
    float*         qko    = pool + NC;
    __nv_bfloat16* att_hi = (__nv_bfloat16*)(pool + 3 * NC);
    __nv_bfloat16* att_lo = (__nv_bfloat16*)(pool + 3 * NC + NCH);
    __nv_bfloat16* ffh_hi = (__nv_bfloat16*)pool;            // 4NC bf16 over [0,2NC) floats
    __nv_bfloat16* ffh_lo = (__nv_bfloat16*)(pool + 2 * NC);
    float*         vproj  = pool + 4 * NC;
    float*         proj   = vproj;
    __nv_bfloat16* x1_hi  = (__nv_bfloat16*)(pool + 5 * NC);
    __nv_bfloat16* x1_lo  = (__nv_bfloat16*)(pool + 5 * NC + NCH);
    float*         ffo    = pool + 5 * NC;
    __nv_bfloat16* cur_hi = (__nv_bfloat16*)(pool + 6 * NC);
    __nv_bfloat16* cur_lo = (__nv_bfloat16*)(pool + 6 * NC + NCH);
    float*         bufA   = pool + 7 * NC;
    float*         bufB   = pool + 8 * NC;
    __nv_bfloat16* wp     = (__nv_bfloat16*)(pool + 9 * NC);

    // weight plane layout (bf16 element offsets)
    __nv_bfloat16* ipw_hi = wp;
    __nv_bfloat16* ipw_lo = wp + 786432;
    __nv_bfloat16* ow_hi  = wp + 1572864;
    __nv_bfloat16* ow_lo  = wp + 1835008;
    __nv_bfloat16* l1w_hi = wp + 2097152;
    __nv_bfloat16* l1w_lo = wp + 3145728;
    __nv_bfloat16* l2w_hi = wp + 4194304;
    __nv_bfloat16* l2w_lo = wp + 5242880;

    const int attn_smem = 2 * SETSZ * CDIM * (int)sizeof(float);  // 73728 B
    cudaFuncSetAttribute(k_attn, cudaFuncAttributeMaxDynamicSharedMemorySize, attn_smem);
    cudaFuncSetAttribute(k_mma_gemm, cudaFuncAttributeMaxDynamicSharedMemorySize, GEMM_SMEM);

    // mask canonicalization + one-time splits (weights, src)
    k_mask_detect<<<1, 256>>>(masks);
    k_mask_convert<<<(MTOT + 255) / 256, 256>>>(masks);
    k_split<<<768, 256>>>(ipw, ipw_hi, ipw_lo, 196608);
    k_split<<<256, 256>>>(ow,  ow_hi,  ow_lo,  65536);
    k_split<<<1024, 256>>>(l1w, l1w_hi, l1w_lo, 262144);
    k_split<<<1024, 256>>>(l2w, l2w_hi, l2w_lo, 262144);
    k_split<<<65538, 256>>>(src, cur_hi, cur_lo, (int)(NC / 4));

    const int gather_blocks = NTOT * 64 / 256;   // 65538
    const int ln_blocks     = NTOT / 8;          // 32769

    const float* cur = src;
    int lid = 0;
    for (int blk = 0; blk < 2; blk++) {
        const float* blockin = cur;
        for (int part = 0; part < 2; part++) {
            const int* ind = inds + (size_t)(blk * 2 + part) * NSETS * SETSZ;
            const unsigned char* msk = maskc + (size_t)(blk * 2 + part) * NSETS * SETSZ;
            const float* posl = pos + (size_t)(blk * 2 + part) * NC;

            // 1. gather -> qk planes
            k_gather_qk<<<gather_blocks, 256>>>(cur, posl, ind, qk_hi, qk_lo);
            // 2. QK in-proj (rows [0,2C)) -> qko fp32
            launch_gemm(qk_hi, qk_lo,
                        ipw_hi + (size_t)lid * 196608, ipw_lo + (size_t)lid * 196608,
                        ipb + (size_t)lid * 3 * CDIM, qko, nullptr, nullptr,
                        NTOT, 2 * CDIM, CDIM, 0);
            // 3. V in-proj from cur planes (rows [2C,3C)) -> vproj fp32
            launch_gemm(cur_hi, cur_lo,
                        ipw_hi + (size_t)lid * 196608 + 131072, ipw_lo + (size_t)lid * 196608 + 131072,
                        ipb + (size_t)lid * 3 * CDIM + 2 * CDIM, vproj, nullptr, nullptr,
                        NTOT, CDIM, CDIM, 0);
            // 4. attention -> att planes
            k_attn<<<NSETS, 256, attn_smem>>>(qko, vproj, ind, msk, att_hi, att_lo);
            // 5. out-proj -> proj fp32
            launch_gemm(att_hi, att_lo,
                        ow_hi + (size_t)lid * 65536, ow_lo + (size_t)lid * 65536,
                        ob + (size_t)lid * CDIM, proj, nullptr, nullptr,
                        NTOT, CDIM, CDIM, 0);
            // 6. scatter + residual + LN1 -> x1 fp32 (lout) + x1 planes
            float* lout = (part == 0) ? bufA : bufB;
            float* x1 = lout;
            k_scatter_ln<<<ln_blocks, 256>>>(cur, proj, ind,
                                             n1g + (size_t)lid * CDIM, n1b + (size_t)lid * CDIM,
                                             x1, x1_hi, x1_lo);
            // 7. FF1 + GELU -> ffh planes
            launch_gemm(x1_hi, x1_lo,
                        l1w_hi + (size_t)lid * 262144, l1w_lo + (size_t)lid * 262144,
                        l1b + (size_t)lid * DFFN, nullptr, ffh_hi, ffh_lo,
                        NTOT, DFFN, CDIM, 1);
            // 8. FF2 -> ffo fp32
            launch_gemm(ffh_hi, ffh_lo,
                        l2w_hi + (size_t)lid * 262144, l2w_lo + (size_t)lid * 262144,
                        l2b + (size_t)lid * CDIM, ffo, nullptr, nullptr,
                        NTOT, CDIM, DFFN, 0);
            // 9. LN2+LN3 in place; emit cur planes for next layer's V when part==0
            k_ln2_ln3<<<ln_blocks, 256>>>(x1, ffo, cur,
                                          n2g + (size_t)lid * CDIM, n2b + (size_t)lid * CDIM,
                                          eg + (size_t)lid * CDIM,  eb + (size_t)lid * CDIM,
                                          lout, cur_hi, cur_lo, part == 0 ? 1 : 0);
            cur = lout;
            lid++;
        }
        // block residual norm -> d_out; emit cur planes for next block's first layer
        k_add_ln<<<ln_blocks, 256>>>(cur, blockin,
                                     rg + (size_t)blk * CDIM, rb + (size_t)blk * CDIM,
                                     outp, cur_hi, cur_lo, blk == 0 ? 1 : 0);
        cur = outp;
    }
}